// round 3
// baseline (speedup 1.0000x reference)
#include <cuda_runtime.h>
#include <math_constants.h>

#define Bb 4
#define Tt 2048
#define Cc 1024
#define Hh 16
#define DH 64
#define TC3 (3*Cc)

// Scratch (allocation-free rule: __device__ globals)
__device__ float g_qkv[(size_t)Bb*Tt*3*Cc];   // 96 MB: qkv projection output
__device__ float g_ao [(size_t)Bb*Tt*Cc];     // 32 MB: attention output (pre out-proj)

// ---------------------------------------------------------------------------
// Tiled SGEMM + bias: C[M,N] = A[M,K] @ B[K,N] + bias[N]
// BM=BN=128, BK=16, 256 threads, 8x8 microtile per thread.
// ---------------------------------------------------------------------------
__global__ __launch_bounds__(256) void sgemm_bias_kernel(
    const float* __restrict__ A, const float* __restrict__ Bm,
    const float* __restrict__ bias, float* __restrict__ Cm,
    int M, int N, int K)
{
    __shared__ float As[16 * 132];   // [k][m], padded row stride 132 (16B-aligned)
    __shared__ float Bs[16 * 128];   // [k][n]

    const int tid = threadIdx.x;
    const int tx = tid & 15, ty = tid >> 4;
    const int m0 = blockIdx.y * 128, n0 = blockIdx.x * 128;

    float acc[8][8];
#pragma unroll
    for (int i = 0; i < 8; ++i)
#pragma unroll
        for (int j = 0; j < 8; ++j) acc[i][j] = 0.0f;

    for (int kt = 0; kt < K; kt += 16) {
        // Load A tile (128 x 16), store transposed into As[k][m]
#pragma unroll
        for (int r = 0; r < 2; ++r) {
            int idx = tid + r * 256;
            int m = idx >> 2, kq = idx & 3;
            float4 v = *(const float4*)(A + (size_t)(m0 + m) * K + kt + kq * 4);
            As[(kq * 4 + 0) * 132 + m] = v.x;
            As[(kq * 4 + 1) * 132 + m] = v.y;
            As[(kq * 4 + 2) * 132 + m] = v.z;
            As[(kq * 4 + 3) * 132 + m] = v.w;
        }
        // Load B tile (16 x 128)
#pragma unroll
        for (int r = 0; r < 2; ++r) {
            int idx = tid + r * 256;
            int row = idx >> 5, c4 = idx & 31;
            *(float4*)&Bs[row * 128 + c4 * 4] =
                *(const float4*)(Bm + (size_t)(kt + row) * N + n0 + c4 * 4);
        }
        __syncthreads();

#pragma unroll
        for (int k = 0; k < 16; ++k) {
            float av[8], bv[8];
            *(float4*)&av[0] = *(float4*)&As[k * 132 + ty * 4];
            *(float4*)&av[4] = *(float4*)&As[k * 132 + 64 + ty * 4];
            *(float4*)&bv[0] = *(float4*)&Bs[k * 128 + tx * 4];
            *(float4*)&bv[4] = *(float4*)&Bs[k * 128 + 64 + tx * 4];
#pragma unroll
            for (int i = 0; i < 8; ++i)
#pragma unroll
                for (int j = 0; j < 8; ++j)
                    acc[i][j] += av[i] * bv[j];
        }
        __syncthreads();
    }

    // Epilogue with bias
#pragma unroll
    for (int ih = 0; ih < 8; ++ih) {
        int gm = m0 + ((ih < 4) ? (ty * 4 + ih) : (64 + ty * 4 + (ih - 4)));
#pragma unroll
        for (int nh = 0; nh < 2; ++nh) {
            int gn = n0 + nh * 64 + tx * 4;
            float4 bb = *(const float4*)(bias + gn);
            float4 rv;
            rv.x = acc[ih][nh * 4 + 0] + bb.x;
            rv.y = acc[ih][nh * 4 + 1] + bb.y;
            rv.z = acc[ih][nh * 4 + 2] + bb.z;
            rv.w = acc[ih][nh * 4 + 3] + bb.w;
            *(float4*)(Cm + (size_t)gm * N + gn) = rv;
        }
    }
}

// ---------------------------------------------------------------------------
// Flash attention (causal), fp32. One block per (q-tile of 64, head, batch).
// 256 threads as (ty,tx) 16x16; thread owns S rows {ty+16i}, cols {tx+16j}
// (strided ownership -> conflict-free LDS with pad-68 rows), and O rows
// {ty+16i}, d-cols {tx*4+j}. P overwrites the K smem buffer.
// ---------------------------------------------------------------------------
#define PAD 68
#define FLASH_SMEM (3 * 64 * PAD * 4)

__global__ __launch_bounds__(256) void flash_attn_kernel()
{
    extern __shared__ float sm[];
    float* Qs = sm;                // 64 x PAD
    float* Ks = sm + 64 * PAD;     // 64 x PAD  (reused as P after S is computed)
    float* Vs = sm + 2 * 64 * PAD; // 64 x PAD

    const int tid = threadIdx.x;
    const int tx = tid & 15, ty = tid >> 4;
    const int qt = blockIdx.x;     // q tile (0..31)
    const int h  = blockIdx.y;
    const int b  = blockIdx.z;
    const int q0 = qt * 64;

    // Load Q tile
    const float* qbase = g_qkv + (size_t)(b * Tt + q0) * TC3 + h * DH;
#pragma unroll
    for (int r = 0; r < 4; ++r) {
        int idx = tid + r * 256;
        int row = idx >> 4, c4 = idx & 15;
        *(float4*)&Qs[row * PAD + c4 * 4] =
            *(const float4*)(qbase + (size_t)row * TC3 + c4 * 4);
    }

    float o[4][4];
#pragma unroll
    for (int i = 0; i < 4; ++i)
#pragma unroll
        for (int j = 0; j < 4; ++j) o[i][j] = 0.0f;
    float m_i[4], l_i[4];
#pragma unroll
    for (int i = 0; i < 4; ++i) { m_i[i] = -1e30f; l_i[i] = 0.0f; }

    const float scale = 0.125f;  // 1/sqrt(64)

    for (int jt = 0; jt <= qt; ++jt) {
        const int k0 = jt * 64;
        const float* kbase = g_qkv + (size_t)(b * Tt + k0) * TC3 + Cc + h * DH;
        const float* vbase = kbase + Cc;

        __syncthreads();   // previous iteration done reading Ks(P)/Vs
#pragma unroll
        for (int r = 0; r < 4; ++r) {
            int idx = tid + r * 256;
            int row = idx >> 4, c4 = idx & 15;
            *(float4*)&Ks[row * PAD + c4 * 4] =
                *(const float4*)(kbase + (size_t)row * TC3 + c4 * 4);
            *(float4*)&Vs[row * PAD + c4 * 4] =
                *(const float4*)(vbase + (size_t)row * TC3 + c4 * 4);
        }
        __syncthreads();

        // S = Q @ K^T (contraction over d=64)
        float s[4][4];
#pragma unroll
        for (int i = 0; i < 4; ++i)
#pragma unroll
            for (int j = 0; j < 4; ++j) s[i][j] = 0.0f;

#pragma unroll
        for (int k4 = 0; k4 < 16; ++k4) {
            float a[4][4], bbv[4][4];
#pragma unroll
            for (int i = 0; i < 4; ++i)
                *(float4*)a[i] = *(float4*)&Qs[(ty + 16 * i) * PAD + k4 * 4];
#pragma unroll
            for (int j = 0; j < 4; ++j)
                *(float4*)bbv[j] = *(float4*)&Ks[(tx + 16 * j) * PAD + k4 * 4];
#pragma unroll
            for (int i = 0; i < 4; ++i)
#pragma unroll
                for (int j = 0; j < 4; ++j)
#pragma unroll
                    for (int u = 0; u < 4; ++u)
                        s[i][j] += a[i][u] * bbv[j][u];
        }

        // Scale + causal mask (only diagonal tile needs masking)
        const bool diag = (jt == qt);
#pragma unroll
        for (int i = 0; i < 4; ++i)
#pragma unroll
            for (int j = 0; j < 4; ++j) {
                float sv = s[i][j] * scale;
                if (diag && (tx + 16 * j) > (ty + 16 * i)) sv = -1e30f;
                s[i][j] = sv;
            }

        // Online softmax update (row reductions over 16-lane groups)
        float alpha[4];
#pragma unroll
        for (int i = 0; i < 4; ++i) {
            float mx = fmaxf(fmaxf(s[i][0], s[i][1]), fmaxf(s[i][2], s[i][3]));
#pragma unroll
            for (int off = 8; off >= 1; off >>= 1)
                mx = fmaxf(mx, __shfl_xor_sync(0xffffffffu, mx, off));
            float mnew = fmaxf(m_i[i], mx);
            float rs = 0.0f;
#pragma unroll
            for (int j = 0; j < 4; ++j) {
                s[i][j] = __expf(s[i][j] - mnew);
                rs += s[i][j];
            }
#pragma unroll
            for (int off = 8; off >= 1; off >>= 1)
                rs += __shfl_xor_sync(0xffffffffu, rs, off);
            alpha[i] = __expf(m_i[i] - mnew);
            l_i[i] = l_i[i] * alpha[i] + rs;
            m_i[i] = mnew;
        }
#pragma unroll
        for (int i = 0; i < 4; ++i)
#pragma unroll
            for (int j = 0; j < 4; ++j) o[i][j] *= alpha[i];

        __syncthreads();   // everyone done reading Ks -> safe to overwrite with P
#pragma unroll
        for (int i = 0; i < 4; ++i)
#pragma unroll
            for (int j = 0; j < 4; ++j)
                Ks[(ty + 16 * i) * PAD + tx + 16 * j] = s[i][j];
        __syncthreads();

        // O += P @ V  (contraction over keys=64)
#pragma unroll
        for (int k4 = 0; k4 < 16; ++k4) {
            float pa[4][4];
#pragma unroll
            for (int i = 0; i < 4; ++i)
                *(float4*)pa[i] = *(float4*)&Ks[(ty + 16 * i) * PAD + k4 * 4];
#pragma unroll
            for (int u = 0; u < 4; ++u) {
                float4 vb = *(float4*)&Vs[(k4 * 4 + u) * PAD + tx * 4];
#pragma unroll
                for (int i = 0; i < 4; ++i) {
                    float pv = pa[i][u];
                    o[i][0] += pv * vb.x;
                    o[i][1] += pv * vb.y;
                    o[i][2] += pv * vb.z;
                    o[i][3] += pv * vb.w;
                }
            }
        }
    }

    // Normalize and write attention output (layout: [b][t][h*DH+d])
#pragma unroll
    for (int i = 0; i < 4; ++i) {
        float inv = 1.0f / l_i[i];
        int gq = q0 + ty + 16 * i;
        float4 rv;
        rv.x = o[i][0] * inv;
        rv.y = o[i][1] * inv;
        rv.z = o[i][2] * inv;
        rv.w = o[i][3] * inv;
        *(float4*)(g_ao + (size_t)(b * Tt + gq) * Cc + h * DH + tx * 4) = rv;
    }
}

// ---------------------------------------------------------------------------
extern "C" void kernel_launch(void* const* d_in, const int* in_sizes, int n_in,
                              void* d_out, int out_size)
{
    const float* x     = (const float*)d_in[0];
    const float* w_qkv = (const float*)d_in[1];
    const float* b_qkv = (const float*)d_in[2];
    const float* w_out = (const float*)d_in[3];
    const float* b_out = (const float*)d_in[4];
    float* out = (float*)d_out;

    void *qkv_p = nullptr, *ao_p = nullptr;
    cudaGetSymbolAddress(&qkv_p, g_qkv);
    cudaGetSymbolAddress(&ao_p, g_ao);

    // 1) QKV projection: (8192 x 1024) @ (1024 x 3072) + b
    sgemm_bias_kernel<<<dim3(TC3 / 128, (Bb * Tt) / 128), 256>>>(
        x, w_qkv, b_qkv, (float*)qkv_p, Bb * Tt, TC3, Cc);

    // 2) Causal flash attention
    cudaFuncSetAttribute(flash_attn_kernel,
                         cudaFuncAttributeMaxDynamicSharedMemorySize, FLASH_SMEM);
    flash_attn_kernel<<<dim3(Tt / 64, Hh, Bb), 256, FLASH_SMEM>>>();

    // 3) Output projection: (8192 x 1024) @ (1024 x 1024) + b
    sgemm_bias_kernel<<<dim3(Cc / 128, (Bb * Tt) / 128), 256>>>(
        (const float*)ao_p, w_out, b_out, out, Bb * Tt, Cc, Cc);
}

// round 6
// speedup vs baseline: 1.4448x; 1.4448x over previous
#include <cuda_runtime.h>
#include <cuda_bf16.h>
#include <cstdint>

#define Bb 4
#define Tt 2048
#define Cc 1024
#define Hh 16
#define DH 64
#define TC3 (3*Cc)
#define MTOT (Bb*Tt)   // 8192

// ---------------- scratch (__device__ globals; no allocation allowed) -------
__device__ float g_qkv[(size_t)MTOT * TC3];   // 96 MB
__device__ float g_ao [(size_t)MTOT * Cc];    // 32 MB
__device__ __nv_bfloat16 g_xhi [(size_t)MTOT * Cc];
__device__ __nv_bfloat16 g_xlo [(size_t)MTOT * Cc];
__device__ __nv_bfloat16 g_aohi[(size_t)MTOT * Cc];
__device__ __nv_bfloat16 g_aolo[(size_t)MTOT * Cc];
__device__ __nv_bfloat16 g_wqkvT_hi[(size_t)TC3 * Cc];
__device__ __nv_bfloat16 g_wqkvT_lo[(size_t)TC3 * Cc];
__device__ __nv_bfloat16 g_woutT_hi[(size_t)Cc * Cc];
__device__ __nv_bfloat16 g_woutT_lo[(size_t)Cc * Cc];

// ---------------- helpers ----------------------------------------------------
__device__ __forceinline__ uint32_t smem_u32(const void* p) {
    uint32_t a;
    asm("{ .reg .u64 t; cvta.to.shared.u64 t, %1; cvt.u32.u64 %0, t; }" : "=r"(a) : "l"(p));
    return a;
}
#define CP_ASYNC16(dst, src) \
    asm volatile("cp.async.cg.shared.global [%0], [%1], 16;" :: "r"(dst), "l"(src))
#define CP_COMMIT() asm volatile("cp.async.commit_group;")
#define CP_WAIT0()  asm volatile("cp.async.wait_group 0;")
#define CP_WAIT1()  asm volatile("cp.async.wait_group 1;")

#define LDSM_X4(r0, r1, r2, r3, a) \
    asm volatile("ldmatrix.sync.aligned.m8n8.x4.shared.b16 {%0,%1,%2,%3}, [%4];" \
                 : "=r"(r0), "=r"(r1), "=r"(r2), "=r"(r3) : "r"(a))

#define MMA_BF16(c0, c1, c2, c3, a0, a1, a2, a3, b0, b1) \
    asm volatile("mma.sync.aligned.m16n8k16.row.col.f32.bf16.bf16.f32 " \
                 "{%0,%1,%2,%3}, {%4,%5,%6,%7}, {%8,%9}, {%0,%1,%2,%3};" \
                 : "+f"(c0), "+f"(c1), "+f"(c2), "+f"(c3) \
                 : "r"(a0), "r"(a1), "r"(a2), "r"(a3), "r"(b0), "r"(b1))

// ---------------- pre-pass: fp32 -> bf16 hi/lo split ------------------------
__global__ void split_kernel(const float* __restrict__ in,
                             __nv_bfloat16* __restrict__ hi,
                             __nv_bfloat16* __restrict__ lo, size_t n4)
{
    size_t i = (size_t)blockIdx.x * blockDim.x + threadIdx.x;
    if (i >= n4) return;
    float4 v = ((const float4*)in)[i];
    ushort4 h, l;
    __nv_bfloat16 t;
    t = __float2bfloat16(v.x); h.x = __bfloat16_as_ushort(t);
    l.x = __bfloat16_as_ushort(__float2bfloat16(v.x - __bfloat162float(t)));
    t = __float2bfloat16(v.y); h.y = __bfloat16_as_ushort(t);
    l.y = __bfloat16_as_ushort(__float2bfloat16(v.y - __bfloat162float(t)));
    t = __float2bfloat16(v.z); h.z = __bfloat16_as_ushort(t);
    l.z = __bfloat16_as_ushort(__float2bfloat16(v.z - __bfloat162float(t)));
    t = __float2bfloat16(v.w); h.w = __bfloat16_as_ushort(t);
    l.w = __bfloat16_as_ushort(__float2bfloat16(v.w - __bfloat162float(t)));
    ((ushort4*)hi)[i] = h;
    ((ushort4*)lo)[i] = l;
}

// W[K,N] fp32 -> WT[N,K] bf16 hi/lo
__global__ __launch_bounds__(256) void transpose_split_kernel(
    const float* __restrict__ W, __nv_bfloat16* __restrict__ Thi,
    __nv_bfloat16* __restrict__ Tlo, int K, int N)
{
    __shared__ float tile[32][33];
    int n0 = blockIdx.x * 32, k0 = blockIdx.y * 32;
    int tx = threadIdx.x & 31, ty = threadIdx.x >> 5;
#pragma unroll
    for (int i = 0; i < 4; ++i)
        tile[ty + 8 * i][tx] = W[(size_t)(k0 + ty + 8 * i) * N + n0 + tx];
    __syncthreads();
#pragma unroll
    for (int i = 0; i < 4; ++i) {
        float v = tile[tx][ty + 8 * i];
        __nv_bfloat16 h = __float2bfloat16(v);
        __nv_bfloat16 l = __float2bfloat16(v - __bfloat162float(h));
        size_t o = (size_t)(n0 + ty + 8 * i) * K + k0 + tx;
        Thi[o] = h; Tlo[o] = l;
    }
}

// ---------------- HMMA GEMM: C = A@B^T + bias, bf16 3-pass split ------------
// A(hi/lo)[M,K], B(hi/lo)[N,K] bf16; C[M,N] fp32.
// CTA tile 128x128, BK=32; 8 warps (4 in M x 2 in N), warp tile 32x64.
// smem rows padded to 80B (conflict-free ldmatrix); double-buffered cp.async.
#define ROWB 80
#define COMP_SZ (128 * ROWB)        // 10240 B per component
#define BUF_SZ  (4 * COMP_SZ)       // 40960 B (Ahi,Alo,Bhi,Blo)
#define GEMM_SMEM (2 * BUF_SZ)      // 81920 B

__global__ __launch_bounds__(256, 2) void gemm_mma_kernel(
    const __nv_bfloat16* __restrict__ Ahi, const __nv_bfloat16* __restrict__ Alo,
    const __nv_bfloat16* __restrict__ Bhi, const __nv_bfloat16* __restrict__ Blo,
    const float* __restrict__ bias, float* __restrict__ Cm,
    int M, int N, int K)
{
    extern __shared__ char smem[];
    const uint32_t sb = smem_u32(smem);
    const int tid = threadIdx.x;
    const int wid = tid >> 5, lane = tid & 31;
    const int wm = wid & 3, wn = wid >> 2;          // warp coords
    const int m0 = blockIdx.y * 128, n0 = blockIdx.x * 128;

    float acc[2][8][4];
#pragma unroll
    for (int i = 0; i < 2; ++i)
#pragma unroll
        for (int j = 0; j < 8; ++j)
#pragma unroll
            for (int t = 0; t < 4; ++t) acc[i][j][t] = 0.0f;

    const int NC = K >> 5;  // 32-wide K chunks

    // per-thread load slots: 8 x 16B cp.asyncs per chunk
    // it 0..7: comp = it>>1, local = tid + (it&1)*256, r = local>>2, c = local&3
#define LOAD_CHUNK(cidx, buf)                                                  \
    do {                                                                       \
        const int k0_ = (cidx) << 5;                                           \
        const uint32_t sdst0 = sb + (buf) * BUF_SZ;                            \
        _Pragma("unroll")                                                      \
        for (int it = 0; it < 8; ++it) {                                       \
            const int comp = it >> 1;                                          \
            const int local = tid + ((it & 1) << 8);                           \
            const int r = local >> 2, ccol = local & 3;                        \
            const __nv_bfloat16* gs = (comp == 0) ? Ahi : (comp == 1) ? Alo    \
                                    : (comp == 2) ? Bhi : Blo;                 \
            const int row = ((comp < 2) ? m0 : n0) + r;                        \
            const __nv_bfloat16* gp = gs + (size_t)row * K + k0_ + ccol * 8;   \
            CP_ASYNC16(sdst0 + comp * COMP_SZ + r * ROWB + ccol * 16, gp);     \
        }                                                                      \
        CP_COMMIT();                                                           \
    } while (0)

    LOAD_CHUNK(0, 0);

    for (int c = 0; c < NC; ++c) {
        const int buf = c & 1;
        if (c + 1 < NC) { LOAD_CHUNK(c + 1, buf ^ 1); CP_WAIT1(); }
        else            { CP_WAIT0(); }
        __syncthreads();

        const uint32_t sbuf = sb + buf * BUF_SZ;
#pragma unroll
        for (int pass = 0; pass < 3; ++pass) {
            const uint32_t aoff = sbuf + ((pass == 2) ? COMP_SZ : 0);
            const uint32_t boff = sbuf + ((pass == 1) ? 3 : 2) * COMP_SZ;
#pragma unroll
            for (int ks = 0; ks < 2; ++ks) {
                uint32_t a[2][4];
#pragma unroll
                for (int mi = 0; mi < 2; ++mi) {
                    uint32_t ad = aoff + (wm * 32 + mi * 16 + (lane & 15)) * ROWB
                                + ks * 32 + ((lane >> 4) << 4);
                    LDSM_X4(a[mi][0], a[mi][1], a[mi][2], a[mi][3], ad);
                }
                uint32_t b[8][2];
#pragma unroll
                for (int p = 0; p < 4; ++p) {
                    uint32_t bd = boff
                        + (wn * 64 + p * 16 + ((lane >> 4) << 3) + (lane & 7)) * ROWB
                        + ks * 32 + (((lane >> 3) & 1) << 4);
                    LDSM_X4(b[2 * p][0], b[2 * p][1], b[2 * p + 1][0], b[2 * p + 1][1], bd);
                }
#pragma unroll
                for (int mi = 0; mi < 2; ++mi)
#pragma unroll
                    for (int ni = 0; ni < 8; ++ni)
                        MMA_BF16(acc[mi][ni][0], acc[mi][ni][1],
                                 acc[mi][ni][2], acc[mi][ni][3],
                                 a[mi][0], a[mi][1], a[mi][2], a[mi][3],
                                 b[ni][0], b[ni][1]);
            }
        }
        __syncthreads();
    }

    // epilogue: D frag thread mapping (row = lane/4 [+8], col = 2*(lane%4))
    const int tr = lane >> 2, tc = (lane & 3) << 1;
#pragma unroll
    for (int mi = 0; mi < 2; ++mi) {
        int mA = m0 + wm * 32 + mi * 16 + tr;
#pragma unroll
        for (int ni = 0; ni < 8; ++ni) {
            int n = n0 + wn * 64 + ni * 8 + tc;
            float b0 = __ldg(bias + n), b1 = __ldg(bias + n + 1);
            float2 v0 = make_float2(acc[mi][ni][0] + b0, acc[mi][ni][1] + b1);
            float2 v1 = make_float2(acc[mi][ni][2] + b0, acc[mi][ni][3] + b1);
            *(float2*)(Cm + (size_t)mA * N + n) = v0;
            *(float2*)(Cm + (size_t)(mA + 8) * N + n) = v1;
        }
    }
}

// ---------------- flash attention (unchanged fp32, validated) ---------------
#define PAD 68
#define FLASH_SMEM (3 * 64 * PAD * 4)

__global__ __launch_bounds__(256) void flash_attn_kernel()
{
    extern __shared__ float sm[];
    float* Qs = sm;
    float* Ks = sm + 64 * PAD;
    float* Vs = sm + 2 * 64 * PAD;

    const int tid = threadIdx.x;
    const int tx = tid & 15, ty = tid >> 4;
    const int qt = blockIdx.x;
    const int h  = blockIdx.y;
    const int b  = blockIdx.z;
    const int q0 = qt * 64;

    const float* qbase = g_qkv + (size_t)(b * Tt + q0) * TC3 + h * DH;
#pragma unroll
    for (int r = 0; r < 4; ++r) {
        int idx = tid + r * 256;
        int row = idx >> 4, c4 = idx & 15;
        *(float4*)&Qs[row * PAD + c4 * 4] =
            *(const float4*)(qbase + (size_t)row * TC3 + c4 * 4);
    }

    float o[4][4];
#pragma unroll
    for (int i = 0; i < 4; ++i)
#pragma unroll
        for (int j = 0; j < 4; ++j) o[i][j] = 0.0f;
    float m_i[4], l_i[4];
#pragma unroll
    for (int i = 0; i < 4; ++i) { m_i[i] = -1e30f; l_i[i] = 0.0f; }

    const float scale = 0.125f;

    for (int jt = 0; jt <= qt; ++jt) {
        const int k0 = jt * 64;
        const float* kbase = g_qkv + (size_t)(b * Tt + k0) * TC3 + Cc + h * DH;
        const float* vbase = kbase + Cc;

        __syncthreads();
#pragma unroll
        for (int r = 0; r < 4; ++r) {
            int idx = tid + r * 256;
            int row = idx >> 4, c4 = idx & 15;
            *(float4*)&Ks[row * PAD + c4 * 4] =
                *(const float4*)(kbase + (size_t)row * TC3 + c4 * 4);
            *(float4*)&Vs[row * PAD + c4 * 4] =
                *(const float4*)(vbase + (size_t)row * TC3 + c4 * 4);
        }
        __syncthreads();

        float s[4][4];
#pragma unroll
        for (int i = 0; i < 4; ++i)
#pragma unroll
            for (int j = 0; j < 4; ++j) s[i][j] = 0.0f;

#pragma unroll
        for (int k4 = 0; k4 < 16; ++k4) {
            float a[4][4], bbv[4][4];
#pragma unroll
            for (int i = 0; i < 4; ++i)
                *(float4*)a[i] = *(float4*)&Qs[(ty + 16 * i) * PAD + k4 * 4];
#pragma unroll
            for (int j = 0; j < 4; ++j)
                *(float4*)bbv[j] = *(float4*)&Ks[(tx + 16 * j) * PAD + k4 * 4];
#pragma unroll
            for (int i = 0; i < 4; ++i)
#pragma unroll
                for (int j = 0; j < 4; ++j)
#pragma unroll
                    for (int u = 0; u < 4; ++u)
                        s[i][j] += a[i][u] * bbv[j][u];
        }

        const bool diag = (jt == qt);
#pragma unroll
        for (int i = 0; i < 4; ++i)
#pragma unroll
            for (int j = 0; j < 4; ++j) {
                float sv = s[i][j] * scale;
                if (diag && (tx + 16 * j) > (ty + 16 * i)) sv = -1e30f;
                s[i][j] = sv;
            }

        float alpha[4];
#pragma unroll
        for (int i = 0; i < 4; ++i) {
            float mx = fmaxf(fmaxf(s[i][0], s[i][1]), fmaxf(s[i][2], s[i][3]));
#pragma unroll
            for (int off = 8; off >= 1; off >>= 1)
                mx = fmaxf(mx, __shfl_xor_sync(0xffffffffu, mx, off));
            float mnew = fmaxf(m_i[i], mx);
            float rs = 0.0f;
#pragma unroll
            for (int j = 0; j < 4; ++j) {
                s[i][j] = __expf(s[i][j] - mnew);
                rs += s[i][j];
            }
#pragma unroll
            for (int off = 8; off >= 1; off >>= 1)
                rs += __shfl_xor_sync(0xffffffffu, rs, off);
            alpha[i] = __expf(m_i[i] - mnew);
            l_i[i] = l_i[i] * alpha[i] + rs;
            m_i[i] = mnew;
        }
#pragma unroll
        for (int i = 0; i < 4; ++i)
#pragma unroll
            for (int j = 0; j < 4; ++j) o[i][j] *= alpha[i];

        __syncthreads();
#pragma unroll
        for (int i = 0; i < 4; ++i)
#pragma unroll
            for (int j = 0; j < 4; ++j)
                Ks[(ty + 16 * i) * PAD + tx + 16 * j] = s[i][j];
        __syncthreads();

#pragma unroll
        for (int k4 = 0; k4 < 16; ++k4) {
            float pa[4][4];
#pragma unroll
            for (int i = 0; i < 4; ++i)
                *(float4*)pa[i] = *(float4*)&Ks[(ty + 16 * i) * PAD + k4 * 4];
#pragma unroll
            for (int u = 0; u < 4; ++u) {
                float4 vb = *(float4*)&Vs[(k4 * 4 + u) * PAD + tx * 4];
#pragma unroll
                for (int i = 0; i < 4; ++i) {
                    float pv = pa[i][u];
                    o[i][0] += pv * vb.x;
                    o[i][1] += pv * vb.y;
                    o[i][2] += pv * vb.z;
                    o[i][3] += pv * vb.w;
                }
            }
        }
    }

#pragma unroll
    for (int i = 0; i < 4; ++i) {
        float inv = 1.0f / l_i[i];
        int gq = q0 + ty + 16 * i;
        float4 rv;
        rv.x = o[i][0] * inv;
        rv.y = o[i][1] * inv;
        rv.z = o[i][2] * inv;
        rv.w = o[i][3] * inv;
        *(float4*)(g_ao + (size_t)(b * Tt + gq) * Cc + h * DH + tx * 4) = rv;
    }
}

// ---------------------------------------------------------------------------
extern "C" void kernel_launch(void* const* d_in, const int* in_sizes, int n_in,
                              void* d_out, int out_size)
{
    const float* x     = (const float*)d_in[0];
    const float* w_qkv = (const float*)d_in[1];
    const float* b_qkv = (const float*)d_in[2];
    const float* w_out = (const float*)d_in[3];
    const float* b_out = (const float*)d_in[4];
    float* out = (float*)d_out;

    void *qkv_p, *ao_p, *xhi_p, *xlo_p, *aohi_p, *aolo_p;
    void *wqh_p, *wql_p, *woh_p, *wol_p;
    cudaGetSymbolAddress(&qkv_p, g_qkv);
    cudaGetSymbolAddress(&ao_p, g_ao);
    cudaGetSymbolAddress(&xhi_p, g_xhi);
    cudaGetSymbolAddress(&xlo_p, g_xlo);
    cudaGetSymbolAddress(&aohi_p, g_aohi);
    cudaGetSymbolAddress(&aolo_p, g_aolo);
    cudaGetSymbolAddress(&wqh_p, g_wqkvT_hi);
    cudaGetSymbolAddress(&wql_p, g_wqkvT_lo);
    cudaGetSymbolAddress(&woh_p, g_woutT_hi);
    cudaGetSymbolAddress(&wol_p, g_woutT_lo);

    const size_t n4x = (size_t)MTOT * Cc / 4;

    split_kernel<<<(unsigned)((n4x + 255) / 256), 256>>>(
        x, (__nv_bfloat16*)xhi_p, (__nv_bfloat16*)xlo_p, n4x);
    transpose_split_kernel<<<dim3(TC3 / 32, Cc / 32), 256>>>(
        w_qkv, (__nv_bfloat16*)wqh_p, (__nv_bfloat16*)wql_p, Cc, TC3);
    transpose_split_kernel<<<dim3(Cc / 32, Cc / 32), 256>>>(
        w_out, (__nv_bfloat16*)woh_p, (__nv_bfloat16*)wol_p, Cc, Cc);

    cudaFuncSetAttribute(gemm_mma_kernel,
                         cudaFuncAttributeMaxDynamicSharedMemorySize, GEMM_SMEM);
    gemm_mma_kernel<<<dim3(TC3 / 128, MTOT / 128), 256, GEMM_SMEM>>>(
        (const __nv_bfloat16*)xhi_p, (const __nv_bfloat16*)xlo_p,
        (const __nv_bfloat16*)wqh_p, (const __nv_bfloat16*)wql_p,
        b_qkv, (float*)qkv_p, MTOT, TC3, Cc);

    cudaFuncSetAttribute(flash_attn_kernel,
                         cudaFuncAttributeMaxDynamicSharedMemorySize, FLASH_SMEM);
    flash_attn_kernel<<<dim3(Tt / 64, Hh, Bb), 256, FLASH_SMEM>>>();

    split_kernel<<<(unsigned)((n4x + 255) / 256), 256>>>(
        (const float*)ao_p, (__nv_bfloat16*)aohi_p, (__nv_bfloat16*)aolo_p, n4x);

    gemm_mma_kernel<<<dim3(Cc / 128, MTOT / 128), 256, GEMM_SMEM>>>(
        (const __nv_bfloat16*)aohi_p, (const __nv_bfloat16*)aolo_p,
        (const __nv_bfloat16*)woh_p, (const __nv_bfloat16*)wol_p,
        b_out, out, MTOT, Cc, Cc);
}

// round 10
// speedup vs baseline: 2.3725x; 1.6422x over previous
#include <cuda_runtime.h>
#include <cuda_bf16.h>
#include <cstdint>

#define Bb 4
#define Tt 2048
#define Cc 1024
#define Hh 16
#define DH 64
#define TC3 (3*Cc)
#define MTOT (Bb*Tt)   // 8192

// ---------------- scratch (__device__ globals; no allocation allowed) -------
__device__ __nv_bfloat16 g_qkvhi[(size_t)MTOT * TC3];  // 48 MB
__device__ __nv_bfloat16 g_qkvlo[(size_t)MTOT * TC3];  // 48 MB
__device__ __nv_bfloat16 g_xhi [(size_t)MTOT * Cc];
__device__ __nv_bfloat16 g_xlo [(size_t)MTOT * Cc];
__device__ __nv_bfloat16 g_aohi[(size_t)MTOT * Cc];
__device__ __nv_bfloat16 g_aolo[(size_t)MTOT * Cc];
__device__ __nv_bfloat16 g_wqkvT_hi[(size_t)TC3 * Cc];
__device__ __nv_bfloat16 g_wqkvT_lo[(size_t)TC3 * Cc];
__device__ __nv_bfloat16 g_woutT_hi[(size_t)Cc * Cc];
__device__ __nv_bfloat16 g_woutT_lo[(size_t)Cc * Cc];

// ---------------- helpers ----------------------------------------------------
__device__ __forceinline__ uint32_t smem_u32(const void* p) {
    uint32_t a;
    asm("{ .reg .u64 t; cvta.to.shared.u64 t, %1; cvt.u32.u64 %0, t; }" : "=r"(a) : "l"(p));
    return a;
}
#define CP_ASYNC16(dst, src) \
    asm volatile("cp.async.cg.shared.global [%0], [%1], 16;" :: "r"(dst), "l"(src))
#define CP_COMMIT() asm volatile("cp.async.commit_group;")
#define CP_WAIT0()  asm volatile("cp.async.wait_group 0;")
#define CP_WAIT1()  asm volatile("cp.async.wait_group 1;")

#define LDSM_X4(r0, r1, r2, r3, a) \
    asm volatile("ldmatrix.sync.aligned.m8n8.x4.shared.b16 {%0,%1,%2,%3}, [%4];" \
                 : "=r"(r0), "=r"(r1), "=r"(r2), "=r"(r3) : "r"(a))
#define LDSM_X4_T(r0, r1, r2, r3, a) \
    asm volatile("ldmatrix.sync.aligned.m8n8.x4.trans.shared.b16 {%0,%1,%2,%3}, [%4];" \
                 : "=r"(r0), "=r"(r1), "=r"(r2), "=r"(r3) : "r"(a))

#define MMA_BF16(c0, c1, c2, c3, a0, a1, a2, a3, b0, b1) \
    asm volatile("mma.sync.aligned.m16n8k16.row.col.f32.bf16.bf16.f32 " \
                 "{%0,%1,%2,%3}, {%4,%5,%6,%7}, {%8,%9}, {%0,%1,%2,%3};" \
                 : "+f"(c0), "+f"(c1), "+f"(c2), "+f"(c3) \
                 : "r"(a0), "r"(a1), "r"(a2), "r"(a3), "r"(b0), "r"(b1))

__device__ __forceinline__ uint32_t pack_bf16(float x, float y) {
    __nv_bfloat162 t = __floats2bfloat162_rn(x, y);
    return *reinterpret_cast<uint32_t*>(&t);
}
__device__ __forceinline__ void split_store2(__nv_bfloat16* Hi, __nv_bfloat16* Lo,
                                             size_t off, float a, float b) {
    __nv_bfloat16 h0 = __float2bfloat16(a);
    __nv_bfloat16 h1 = __float2bfloat16(b);
    float r0 = a - __bfloat162float(h0);
    float r1 = b - __bfloat162float(h1);
    ushort2 hh = make_ushort2(__bfloat16_as_ushort(h0), __bfloat16_as_ushort(h1));
    ushort2 ll = make_ushort2(__bfloat16_as_ushort(__float2bfloat16(r0)),
                              __bfloat16_as_ushort(__float2bfloat16(r1)));
    *(ushort2*)(Hi + off) = hh;
    *(ushort2*)(Lo + off) = ll;
}

// ---------------- pre-pass: fp32 -> bf16 hi/lo split ------------------------
__global__ void split_kernel(const float* __restrict__ in,
                             __nv_bfloat16* __restrict__ hi,
                             __nv_bfloat16* __restrict__ lo, size_t n4)
{
    size_t i = (size_t)blockIdx.x * blockDim.x + threadIdx.x;
    if (i >= n4) return;
    float4 v = ((const float4*)in)[i];
    ushort4 h, l;
    __nv_bfloat16 t;
    t = __float2bfloat16(v.x); h.x = __bfloat16_as_ushort(t);
    l.x = __bfloat16_as_ushort(__float2bfloat16(v.x - __bfloat162float(t)));
    t = __float2bfloat16(v.y); h.y = __bfloat16_as_ushort(t);
    l.y = __bfloat16_as_ushort(__float2bfloat16(v.y - __bfloat162float(t)));
    t = __float2bfloat16(v.z); h.z = __bfloat16_as_ushort(t);
    l.z = __bfloat16_as_ushort(__float2bfloat16(v.z - __bfloat162float(t)));
    t = __float2bfloat16(v.w); h.w = __bfloat16_as_ushort(t);
    l.w = __bfloat16_as_ushort(__float2bfloat16(v.w - __bfloat162float(t)));
    ((ushort4*)hi)[i] = h;
    ((ushort4*)lo)[i] = l;
}

// W[K,N] fp32 -> WT[N,K] bf16 hi/lo
__global__ __launch_bounds__(256) void transpose_split_kernel(
    const float* __restrict__ W, __nv_bfloat16* __restrict__ Thi,
    __nv_bfloat16* __restrict__ Tlo, int K, int N)
{
    __shared__ float tile[32][33];
    int n0 = blockIdx.x * 32, k0 = blockIdx.y * 32;
    int tx = threadIdx.x & 31, ty = threadIdx.x >> 5;
#pragma unroll
    for (int i = 0; i < 4; ++i)
        tile[ty + 8 * i][tx] = W[(size_t)(k0 + ty + 8 * i) * N + n0 + tx];
    __syncthreads();
#pragma unroll
    for (int i = 0; i < 4; ++i) {
        float v = tile[tx][ty + 8 * i];
        __nv_bfloat16 h = __float2bfloat16(v);
        __nv_bfloat16 l = __float2bfloat16(v - __bfloat162float(h));
        size_t o = (size_t)(n0 + ty + 8 * i) * K + k0 + tx;
        Thi[o] = h; Tlo[o] = l;
    }
}

// ---------------- HMMA GEMM: C = A@B^T + bias, bf16 3-pass split ------------
// split_out=1: write C as bf16 hi/lo pair; else fp32.
#define ROWB 80
#define COMP_SZ (128 * ROWB)
#define BUF_SZ  (4 * COMP_SZ)
#define GEMM_SMEM (2 * BUF_SZ)

__global__ __launch_bounds__(256, 2) void gemm_mma_kernel(
    const __nv_bfloat16* __restrict__ Ahi, const __nv_bfloat16* __restrict__ Alo,
    const __nv_bfloat16* __restrict__ Bhi, const __nv_bfloat16* __restrict__ Blo,
    const float* __restrict__ bias, float* __restrict__ Cf,
    __nv_bfloat16* __restrict__ Chi, __nv_bfloat16* __restrict__ Clo,
    int M, int N, int K, int split_out)
{
    extern __shared__ char smem[];
    const uint32_t sb = smem_u32(smem);
    const int tid = threadIdx.x;
    const int wid = tid >> 5, lane = tid & 31;
    const int wm = wid & 3, wn = wid >> 2;
    const int m0 = blockIdx.y * 128, n0 = blockIdx.x * 128;

    float acc[2][8][4];
#pragma unroll
    for (int i = 0; i < 2; ++i)
#pragma unroll
        for (int j = 0; j < 8; ++j)
#pragma unroll
            for (int t = 0; t < 4; ++t) acc[i][j][t] = 0.0f;

    const int NC = K >> 5;

#define LOAD_CHUNK(cidx, buf)                                                  \
    do {                                                                       \
        const int k0_ = (cidx) << 5;                                           \
        const uint32_t sdst0 = sb + (buf) * BUF_SZ;                            \
        _Pragma("unroll")                                                      \
        for (int it = 0; it < 8; ++it) {                                       \
            const int comp = it >> 1;                                          \
            const int local = tid + ((it & 1) << 8);                           \
            const int r = local >> 2, ccol = local & 3;                        \
            const __nv_bfloat16* gs = (comp == 0) ? Ahi : (comp == 1) ? Alo    \
                                    : (comp == 2) ? Bhi : Blo;                 \
            const int row = ((comp < 2) ? m0 : n0) + r;                        \
            const __nv_bfloat16* gp = gs + (size_t)row * K + k0_ + ccol * 8;   \
            CP_ASYNC16(sdst0 + comp * COMP_SZ + r * ROWB + ccol * 16, gp);     \
        }                                                                      \
        CP_COMMIT();                                                           \
    } while (0)

    LOAD_CHUNK(0, 0);

    for (int c = 0; c < NC; ++c) {
        const int buf = c & 1;
        if (c + 1 < NC) { LOAD_CHUNK(c + 1, buf ^ 1); CP_WAIT1(); }
        else            { CP_WAIT0(); }
        __syncthreads();

        const uint32_t sbuf = sb + buf * BUF_SZ;
#pragma unroll
        for (int pass = 0; pass < 3; ++pass) {
            const uint32_t aoff = sbuf + ((pass == 2) ? COMP_SZ : 0);
            const uint32_t boff = sbuf + ((pass == 1) ? 3 : 2) * COMP_SZ;
#pragma unroll
            for (int ks = 0; ks < 2; ++ks) {
                uint32_t a[2][4];
#pragma unroll
                for (int mi = 0; mi < 2; ++mi) {
                    uint32_t ad = aoff + (wm * 32 + mi * 16 + (lane & 15)) * ROWB
                                + ks * 32 + ((lane >> 4) << 4);
                    LDSM_X4(a[mi][0], a[mi][1], a[mi][2], a[mi][3], ad);
                }
                uint32_t b[8][2];
#pragma unroll
                for (int p = 0; p < 4; ++p) {
                    uint32_t bd = boff
                        + (wn * 64 + p * 16 + ((lane >> 4) << 3) + (lane & 7)) * ROWB
                        + ks * 32 + (((lane >> 3) & 1) << 4);
                    LDSM_X4(b[2 * p][0], b[2 * p][1], b[2 * p + 1][0], b[2 * p + 1][1], bd);
                }
#pragma unroll
                for (int mi = 0; mi < 2; ++mi)
#pragma unroll
                    for (int ni = 0; ni < 8; ++ni)
                        MMA_BF16(acc[mi][ni][0], acc[mi][ni][1],
                                 acc[mi][ni][2], acc[mi][ni][3],
                                 a[mi][0], a[mi][1], a[mi][2], a[mi][3],
                                 b[ni][0], b[ni][1]);
            }
        }
        __syncthreads();
    }

    const int tr = lane >> 2, tc = (lane & 3) << 1;
#pragma unroll
    for (int mi = 0; mi < 2; ++mi) {
        int mA = m0 + wm * 32 + mi * 16 + tr;
#pragma unroll
        for (int ni = 0; ni < 8; ++ni) {
            int n = n0 + wn * 64 + ni * 8 + tc;
            float b0 = __ldg(bias + n), b1 = __ldg(bias + n + 1);
            float v00 = acc[mi][ni][0] + b0, v01 = acc[mi][ni][1] + b1;
            float v10 = acc[mi][ni][2] + b0, v11 = acc[mi][ni][3] + b1;
            if (split_out) {
                split_store2(Chi, Clo, (size_t)mA * N + n, v00, v01);
                split_store2(Chi, Clo, (size_t)(mA + 8) * N + n, v10, v11);
            } else {
                *(float2*)(Cf + (size_t)mA * N + n) = make_float2(v00, v01);
                *(float2*)(Cf + (size_t)(mA + 8) * N + n) = make_float2(v10, v11);
            }
        }
    }
}

// ---------------- tensor-core flash attention (causal) ----------------------
// CTA: 128 q-rows (8 warps x 16), K-tiles of 64, hi/lo 3-pass HMMA for S & PV.
// smem: Q hi/lo [128x64] + 2 x KV buffers (Khi,Klo,Vhi,Vlo each [64x64]).
#define FROW 144                         // 64 bf16 cols = 128B + 16B pad
#define Q_SZ   (128 * FROW)              // 18432 per comp
#define KV_SZ  (64 * FROW)               // 9216 per comp
#define KVBUF  (4 * KV_SZ)               // 36864 per buffer
#define FLASH_SMEM (2 * Q_SZ + 2 * KVBUF)  // 110592

__global__ __launch_bounds__(256) void flash_attn_mma_kernel()
{
    extern __shared__ char smem[];
    const uint32_t sb = smem_u32(smem);
    const uint32_t Qhi_b = sb, Qlo_b = sb + Q_SZ;
    const uint32_t KV0 = sb + 2 * Q_SZ;

    const int tid = threadIdx.x;
    const int wid = tid >> 5, lane = tid & 31;
    const int qt = blockIdx.x, h = blockIdx.y, b = blockIdx.z;
    const int q0 = qt * 128;
    const int NT = 2 * qt + 2;

    const __nv_bfloat16* qkvhi = g_qkvhi;
    const __nv_bfloat16* qkvlo = g_qkvlo;

    // ---- issue Q (hi/lo) + KV tile 0 as group 0 ----
    {
        // Q: 2 comps x 128 rows x 8 chunks = 2048 -> 8/thread
#pragma unroll
        for (int it = 0; it < 8; ++it) {
            int gid = tid + (it << 8);
            int comp = gid >> 10;
            int rem = gid & 1023;
            int r = rem >> 3, ch = rem & 7;
            const __nv_bfloat16* src = (comp ? qkvlo : qkvhi)
                + (size_t)(b * Tt + q0 + r) * TC3 + h * DH + ch * 8;
            CP_ASYNC16((comp ? Qlo_b : Qhi_b) + r * FROW + ch * 16, src);
        }
    }
#define LOAD_KV(jt_, buf_)                                                     \
    do {                                                                       \
        const int k0_ = (jt_) * 64;                                            \
        const uint32_t base_ = KV0 + (buf_) * KVBUF;                           \
        _Pragma("unroll")                                                      \
        for (int it = 0; it < 8; ++it) {                                       \
            int gid = tid + (it << 8);                                         \
            int comp = gid >> 9;       /* 0:Khi 1:Klo 2:Vhi 3:Vlo */           \
            int rem = gid & 511;                                               \
            int r = rem >> 3, ch = rem & 7;                                    \
            int colb = ((comp < 2) ? Cc : 2 * Cc) + h * DH + ch * 8;           \
            const __nv_bfloat16* src = ((comp & 1) ? qkvlo : qkvhi)            \
                + (size_t)(b * Tt + k0_ + r) * TC3 + colb;                     \
            CP_ASYNC16(base_ + comp * KV_SZ + r * FROW + ch * 16, src);        \
        }                                                                      \
    } while (0)

    LOAD_KV(0, 0);
    CP_COMMIT();

    float o[8][4];
#pragma unroll
    for (int n = 0; n < 8; ++n)
#pragma unroll
        for (int t = 0; t < 4; ++t) o[n][t] = 0.0f;
    float m1 = -1e30f, m2 = -1e30f, l1 = 0.0f, l2 = 0.0f;

    const int row1 = q0 + wid * 16 + (lane >> 2);
    const int row2 = row1 + 8;
    const float scale = 0.125f;

    for (int jt = 0; jt < NT; ++jt) {
        if (jt + 1 < NT) { LOAD_KV(jt + 1, (jt + 1) & 1); CP_COMMIT(); CP_WAIT1(); }
        else             { CP_WAIT0(); }
        __syncthreads();

        const uint32_t kb_hi = KV0 + (jt & 1) * KVBUF;
        const uint32_t kb_lo = kb_hi + KV_SZ;
        const uint32_t vb_hi = kb_hi + 2 * KV_SZ;
        const uint32_t vb_lo = kb_hi + 3 * KV_SZ;
        const int k0 = jt * 64;

        // ---- S = Q@K^T, 3-pass hi/lo ----
        float s[8][4];
#pragma unroll
        for (int n = 0; n < 8; ++n)
#pragma unroll
            for (int t = 0; t < 4; ++t) s[n][t] = 0.0f;

#pragma unroll
        for (int kk = 0; kk < 4; ++kk) {
            const uint32_t a_off = (wid * 16 + (lane & 15)) * FROW
                                 + kk * 32 + ((lane >> 4) << 4);
            uint32_t aqh[4], aql[4];
            LDSM_X4(aqh[0], aqh[1], aqh[2], aqh[3], Qhi_b + a_off);
            LDSM_X4(aql[0], aql[1], aql[2], aql[3], Qlo_b + a_off);
            uint32_t bh[8][2], bl[8][2];
#pragma unroll
            for (int p = 0; p < 4; ++p) {
                const uint32_t b_off = (p * 16 + ((lane >> 4) << 3) + (lane & 7)) * FROW
                                     + kk * 32 + (((lane >> 3) & 1) << 4);
                LDSM_X4(bh[2 * p][0], bh[2 * p][1], bh[2 * p + 1][0], bh[2 * p + 1][1],
                        kb_hi + b_off);
                LDSM_X4(bl[2 * p][0], bl[2 * p][1], bl[2 * p + 1][0], bl[2 * p + 1][1],
                        kb_lo + b_off);
            }
#pragma unroll
            for (int n = 0; n < 8; ++n) {
                MMA_BF16(s[n][0], s[n][1], s[n][2], s[n][3],
                         aqh[0], aqh[1], aqh[2], aqh[3], bh[n][0], bh[n][1]);
                MMA_BF16(s[n][0], s[n][1], s[n][2], s[n][3],
                         aql[0], aql[1], aql[2], aql[3], bh[n][0], bh[n][1]);
                MMA_BF16(s[n][0], s[n][1], s[n][2], s[n][3],
                         aqh[0], aqh[1], aqh[2], aqh[3], bl[n][0], bl[n][1]);
            }
        }

        // ---- scale + causal mask (branchless; exact for all tiles) ----
        const int cb = k0 + ((lane & 3) << 1);
#pragma unroll
        for (int n = 0; n < 8; ++n) {
            int c0 = cb + n * 8, c1 = c0 + 1;
            s[n][0] = (c0 > row1) ? -1e30f : s[n][0] * scale;
            s[n][1] = (c1 > row1) ? -1e30f : s[n][1] * scale;
            s[n][2] = (c0 > row2) ? -1e30f : s[n][2] * scale;
            s[n][3] = (c1 > row2) ? -1e30f : s[n][3] * scale;
        }

        // ---- online softmax (quad reductions) ----
        float mx1 = -1e30f, mx2 = -1e30f;
#pragma unroll
        for (int n = 0; n < 8; ++n) {
            mx1 = fmaxf(mx1, fmaxf(s[n][0], s[n][1]));
            mx2 = fmaxf(mx2, fmaxf(s[n][2], s[n][3]));
        }
        mx1 = fmaxf(mx1, __shfl_xor_sync(0xffffffffu, mx1, 1));
        mx1 = fmaxf(mx1, __shfl_xor_sync(0xffffffffu, mx1, 2));
        mx2 = fmaxf(mx2, __shfl_xor_sync(0xffffffffu, mx2, 1));
        mx2 = fmaxf(mx2, __shfl_xor_sync(0xffffffffu, mx2, 2));
        float mn1 = fmaxf(m1, mx1), mn2 = fmaxf(m2, mx2);
        float rs1 = 0.0f, rs2 = 0.0f;
#pragma unroll
        for (int n = 0; n < 8; ++n) {
            s[n][0] = __expf(s[n][0] - mn1);
            s[n][1] = __expf(s[n][1] - mn1);
            s[n][2] = __expf(s[n][2] - mn2);
            s[n][3] = __expf(s[n][3] - mn2);
            rs1 += s[n][0] + s[n][1];
            rs2 += s[n][2] + s[n][3];
        }
        rs1 += __shfl_xor_sync(0xffffffffu, rs1, 1);
        rs1 += __shfl_xor_sync(0xffffffffu, rs1, 2);
        rs2 += __shfl_xor_sync(0xffffffffu, rs2, 1);
        rs2 += __shfl_xor_sync(0xffffffffu, rs2, 2);
        float al1 = __expf(m1 - mn1), al2 = __expf(m2 - mn2);
        l1 = l1 * al1 + rs1; m1 = mn1;
        l2 = l2 * al2 + rs2; m2 = mn2;
#pragma unroll
        for (int n = 0; n < 8; ++n) {
            o[n][0] *= al1; o[n][1] *= al1;
            o[n][2] *= al2; o[n][3] *= al2;
        }

        // ---- P -> bf16 hi/lo A-fragments (register-only repack) ----
        uint32_t phi[4][4], plo[4][4];
#pragma unroll
        for (int kk = 0; kk < 4; ++kk) {
            float p00 = s[2 * kk][0],     p01 = s[2 * kk][1];
            float p10 = s[2 * kk][2],     p11 = s[2 * kk][3];
            float p20 = s[2 * kk + 1][0], p21 = s[2 * kk + 1][1];
            float p30 = s[2 * kk + 1][2], p31 = s[2 * kk + 1][3];
            phi[kk][0] = pack_bf16(p00, p01);
            phi[kk][1] = pack_bf16(p10, p11);
            phi[kk][2] = pack_bf16(p20, p21);
            phi[kk][3] = pack_bf16(p30, p31);
            __nv_bfloat162* hp;
            hp = (__nv_bfloat162*)&phi[kk][0];
            plo[kk][0] = pack_bf16(p00 - __bfloat162float(hp->x), p01 - __bfloat162float(hp->y));
            hp = (__nv_bfloat162*)&phi[kk][1];
            plo[kk][1] = pack_bf16(p10 - __bfloat162float(hp->x), p11 - __bfloat162float(hp->y));
            hp = (__nv_bfloat162*)&phi[kk][2];
            plo[kk][2] = pack_bf16(p20 - __bfloat162float(hp->x), p21 - __bfloat162float(hp->y));
            hp = (__nv_bfloat162*)&phi[kk][3];
            plo[kk][3] = pack_bf16(p30 - __bfloat162float(hp->x), p31 - __bfloat162float(hp->y));
        }

        // ---- O += P@V, 3-pass (PhiVhi, PloVhi, PhiVlo) ----
#pragma unroll
        for (int kk = 0; kk < 4; ++kk) {
            uint32_t bv[8][2];
#pragma unroll
            for (int p = 0; p < 4; ++p) {
                const uint32_t v_off = (kk * 16 + (lane & 15)) * FROW
                                     + p * 32 + ((lane >> 4) << 4);
                LDSM_X4_T(bv[2 * p][0], bv[2 * p][1], bv[2 * p + 1][0], bv[2 * p + 1][1],
                          vb_hi + v_off);
            }
#pragma unroll
            for (int n = 0; n < 8; ++n) {
                MMA_BF16(o[n][0], o[n][1], o[n][2], o[n][3],
                         phi[kk][0], phi[kk][1], phi[kk][2], phi[kk][3],
                         bv[n][0], bv[n][1]);
                MMA_BF16(o[n][0], o[n][1], o[n][2], o[n][3],
                         plo[kk][0], plo[kk][1], plo[kk][2], plo[kk][3],
                         bv[n][0], bv[n][1]);
            }
#pragma unroll
            for (int p = 0; p < 4; ++p) {
                const uint32_t v_off = (kk * 16 + (lane & 15)) * FROW
                                     + p * 32 + ((lane >> 4) << 4);
                LDSM_X4_T(bv[2 * p][0], bv[2 * p][1], bv[2 * p + 1][0], bv[2 * p + 1][1],
                          vb_lo + v_off);
            }
#pragma unroll
            for (int n = 0; n < 8; ++n)
                MMA_BF16(o[n][0], o[n][1], o[n][2], o[n][3],
                         phi[kk][0], phi[kk][1], phi[kk][2], phi[kk][3],
                         bv[n][0], bv[n][1]);
        }
        __syncthreads();
    }

    // ---- normalize + write hi/lo attention output ----
    const float inv1 = 1.0f / l1, inv2 = 1.0f / l2;
    const size_t r1off = (size_t)(b * Tt + row1) * Cc + h * DH + ((lane & 3) << 1);
    const size_t r2off = (size_t)(b * Tt + row2) * Cc + h * DH + ((lane & 3) << 1);
#pragma unroll
    for (int n = 0; n < 8; ++n) {
        split_store2(g_aohi, g_aolo, r1off + n * 8, o[n][0] * inv1, o[n][1] * inv1);
        split_store2(g_aohi, g_aolo, r2off + n * 8, o[n][2] * inv2, o[n][3] * inv2);
    }
}

// ---------------------------------------------------------------------------
extern "C" void kernel_launch(void* const* d_in, const int* in_sizes, int n_in,
                              void* d_out, int out_size)
{
    const float* x     = (const float*)d_in[0];
    const float* w_qkv = (const float*)d_in[1];
    const float* b_qkv = (const float*)d_in[2];
    const float* w_out = (const float*)d_in[3];
    const float* b_out = (const float*)d_in[4];
    float* out = (float*)d_out;

    void *qkvhi_p, *qkvlo_p, *xhi_p, *xlo_p, *aohi_p, *aolo_p;
    void *wqh_p, *wql_p, *woh_p, *wol_p;
    cudaGetSymbolAddress(&qkvhi_p, g_qkvhi);
    cudaGetSymbolAddress(&qkvlo_p, g_qkvlo);
    cudaGetSymbolAddress(&xhi_p, g_xhi);
    cudaGetSymbolAddress(&xlo_p, g_xlo);
    cudaGetSymbolAddress(&aohi_p, g_aohi);
    cudaGetSymbolAddress(&aolo_p, g_aolo);
    cudaGetSymbolAddress(&wqh_p, g_wqkvT_hi);
    cudaGetSymbolAddress(&wql_p, g_wqkvT_lo);
    cudaGetSymbolAddress(&woh_p, g_woutT_hi);
    cudaGetSymbolAddress(&wol_p, g_woutT_lo);

    const size_t n4x = (size_t)MTOT * Cc / 4;

    split_kernel<<<(unsigned)((n4x + 255) / 256), 256>>>(
        x, (__nv_bfloat16*)xhi_p, (__nv_bfloat16*)xlo_p, n4x);
    transpose_split_kernel<<<dim3(TC3 / 32, Cc / 32), 256>>>(
        w_qkv, (__nv_bfloat16*)wqh_p, (__nv_bfloat16*)wql_p, Cc, TC3);
    transpose_split_kernel<<<dim3(Cc / 32, Cc / 32), 256>>>(
        w_out, (__nv_bfloat16*)woh_p, (__nv_bfloat16*)wol_p, Cc, Cc);

    cudaFuncSetAttribute(gemm_mma_kernel,
                         cudaFuncAttributeMaxDynamicSharedMemorySize, GEMM_SMEM);
    // QKV projection -> bf16 hi/lo qkv (fused split epilogue)
    gemm_mma_kernel<<<dim3(TC3 / 128, MTOT / 128), 256, GEMM_SMEM>>>(
        (const __nv_bfloat16*)xhi_p, (const __nv_bfloat16*)xlo_p,
        (const __nv_bfloat16*)wqh_p, (const __nv_bfloat16*)wql_p,
        b_qkv, nullptr,
        (__nv_bfloat16*)qkvhi_p, (__nv_bfloat16*)qkvlo_p,
        MTOT, TC3, Cc, 1);

    // tensor-core causal flash attention -> bf16 hi/lo ao
    cudaFuncSetAttribute(flash_attn_mma_kernel,
                         cudaFuncAttributeMaxDynamicSharedMemorySize, FLASH_SMEM);
    flash_attn_mma_kernel<<<dim3(Tt / 128, Hh, Bb), 256, FLASH_SMEM>>>();

    // output projection -> fp32 out
    gemm_mma_kernel<<<dim3(Cc / 128, MTOT / 128), 256, GEMM_SMEM>>>(
        (const __nv_bfloat16*)aohi_p, (const __nv_bfloat16*)aolo_p,
        (const __nv_bfloat16*)woh_p, (const __nv_bfloat16*)wol_p,
        b_out, out, nullptr, nullptr, MTOT, Cc, Cc, 0);
}

// round 13
// speedup vs baseline: 2.4266x; 1.0228x over previous
#include <cuda_runtime.h>
#include <cuda_bf16.h>
#include <cstdint>

#define Bb 4
#define Tt 2048
#define Cc 1024
#define Hh 16
#define DH 64
#define TC3 (3*Cc)
#define MTOT (Bb*Tt)   // 8192

// ---------------- scratch (__device__ globals; no allocation allowed) -------
__device__ __nv_bfloat16 g_qkvhi[(size_t)MTOT * TC3];  // 48 MB
__device__ __nv_bfloat16 g_qkvlo[(size_t)MTOT * TC3];  // 48 MB
__device__ __nv_bfloat16 g_xhi [(size_t)MTOT * Cc];
__device__ __nv_bfloat16 g_xlo [(size_t)MTOT * Cc];
__device__ __nv_bfloat16 g_aohi[(size_t)MTOT * Cc];
__device__ __nv_bfloat16 g_aolo[(size_t)MTOT * Cc];
__device__ __nv_bfloat16 g_wqkvT_hi[(size_t)TC3 * Cc];
__device__ __nv_bfloat16 g_wqkvT_lo[(size_t)TC3 * Cc];
__device__ __nv_bfloat16 g_woutT_hi[(size_t)Cc * Cc];
__device__ __nv_bfloat16 g_woutT_lo[(size_t)Cc * Cc];

// ---------------- helpers ----------------------------------------------------
__device__ __forceinline__ uint32_t smem_u32(const void* p) {
    uint32_t a;
    asm("{ .reg .u64 t; cvta.to.shared.u64 t, %1; cvt.u32.u64 %0, t; }" : "=r"(a) : "l"(p));
    return a;
}
#define CP_ASYNC16(dst, src) \
    asm volatile("cp.async.cg.shared.global [%0], [%1], 16;" :: "r"(dst), "l"(src))
#define CP_COMMIT() asm volatile("cp.async.commit_group;")
#define CP_WAIT0()  asm volatile("cp.async.wait_group 0;")
#define CP_WAIT1()  asm volatile("cp.async.wait_group 1;")

#define LDSM_X4(r0, r1, r2, r3, a) \
    asm volatile("ldmatrix.sync.aligned.m8n8.x4.shared.b16 {%0,%1,%2,%3}, [%4];" \
                 : "=r"(r0), "=r"(r1), "=r"(r2), "=r"(r3) : "r"(a))
#define LDSM_X4_T(r0, r1, r2, r3, a) \
    asm volatile("ldmatrix.sync.aligned.m8n8.x4.trans.shared.b16 {%0,%1,%2,%3}, [%4];" \
                 : "=r"(r0), "=r"(r1), "=r"(r2), "=r"(r3) : "r"(a))

#define MMA_BF16(c0, c1, c2, c3, a0, a1, a2, a3, b0, b1) \
    asm volatile("mma.sync.aligned.m16n8k16.row.col.f32.bf16.bf16.f32 " \
                 "{%0,%1,%2,%3}, {%4,%5,%6,%7}, {%8,%9}, {%0,%1,%2,%3};" \
                 : "+f"(c0), "+f"(c1), "+f"(c2), "+f"(c3) \
                 : "r"(a0), "r"(a1), "r"(a2), "r"(a3), "r"(b0), "r"(b1))

__device__ __forceinline__ uint32_t pack_bf16(float x, float y) {
    __nv_bfloat162 t = __floats2bfloat162_rn(x, y);
    return *reinterpret_cast<uint32_t*>(&t);
}
__device__ __forceinline__ void split_store2(__nv_bfloat16* Hi, __nv_bfloat16* Lo,
                                             size_t off, float a, float b) {
    __nv_bfloat16 h0 = __float2bfloat16(a);
    __nv_bfloat16 h1 = __float2bfloat16(b);
    float r0 = a - __bfloat162float(h0);
    float r1 = b - __bfloat162float(h1);
    ushort2 hh = make_ushort2(__bfloat16_as_ushort(h0), __bfloat16_as_ushort(h1));
    ushort2 ll = make_ushort2(__bfloat16_as_ushort(__float2bfloat16(r0)),
                              __bfloat16_as_ushort(__float2bfloat16(r1)));
    *(ushort2*)(Hi + off) = hh;
    *(ushort2*)(Lo + off) = ll;
}

// ---------------- pre-pass: fp32 -> bf16 hi/lo split ------------------------
__global__ void split_kernel(const float* __restrict__ in,
                             __nv_bfloat16* __restrict__ hi,
                             __nv_bfloat16* __restrict__ lo, size_t n4)
{
    size_t i = (size_t)blockIdx.x * blockDim.x + threadIdx.x;
    if (i >= n4) return;
    float4 v = ((const float4*)in)[i];
    ushort4 h, l;
    __nv_bfloat16 t;
    t = __float2bfloat16(v.x); h.x = __bfloat16_as_ushort(t);
    l.x = __bfloat16_as_ushort(__float2bfloat16(v.x - __bfloat162float(t)));
    t = __float2bfloat16(v.y); h.y = __bfloat16_as_ushort(t);
    l.y = __bfloat16_as_ushort(__float2bfloat16(v.y - __bfloat162float(t)));
    t = __float2bfloat16(v.z); h.z = __bfloat16_as_ushort(t);
    l.z = __bfloat16_as_ushort(__float2bfloat16(v.z - __bfloat162float(t)));
    t = __float2bfloat16(v.w); h.w = __bfloat16_as_ushort(t);
    l.w = __bfloat16_as_ushort(__float2bfloat16(v.w - __bfloat162float(t)));
    ((ushort4*)hi)[i] = h;
    ((ushort4*)lo)[i] = l;
}

// W[K,N] fp32 -> WT[N,K] bf16 hi/lo
__global__ __launch_bounds__(256) void transpose_split_kernel(
    const float* __restrict__ W, __nv_bfloat16* __restrict__ Thi,
    __nv_bfloat16* __restrict__ Tlo, int K, int N)
{
    __shared__ float tile[32][33];
    int n0 = blockIdx.x * 32, k0 = blockIdx.y * 32;
    int tx = threadIdx.x & 31, ty = threadIdx.x >> 5;
#pragma unroll
    for (int i = 0; i < 4; ++i)
        tile[ty + 8 * i][tx] = W[(size_t)(k0 + ty + 8 * i) * N + n0 + tx];
    __syncthreads();
#pragma unroll
    for (int i = 0; i < 4; ++i) {
        float v = tile[tx][ty + 8 * i];
        __nv_bfloat16 h = __float2bfloat16(v);
        __nv_bfloat16 l = __float2bfloat16(v - __bfloat162float(h));
        size_t o = (size_t)(n0 + ty + 8 * i) * K + k0 + tx;
        Thi[o] = h; Tlo[o] = l;
    }
}

// ---------------- HMMA GEMM: C = A@B^T + bias, bf16 3-pass split ------------
// Fragment-hoisted: per ks load Ahi,Alo,Bhi once -> 2 MMA passes,
// overwrite B regs with Blo -> 1 MMA pass.  12 LDSM / 48 MMA per ks.
#define ROWB 80
#define COMP_SZ (128 * ROWB)
#define BUF_SZ  (4 * COMP_SZ)
#define GEMM_SMEM (2 * BUF_SZ)

__global__ __launch_bounds__(256, 2) void gemm_mma_kernel(
    const __nv_bfloat16* __restrict__ Ahi, const __nv_bfloat16* __restrict__ Alo,
    const __nv_bfloat16* __restrict__ Bhi, const __nv_bfloat16* __restrict__ Blo,
    const float* __restrict__ bias, float* __restrict__ Cf,
    __nv_bfloat16* __restrict__ Chi, __nv_bfloat16* __restrict__ Clo,
    int M, int N, int K, int split_out)
{
    extern __shared__ char smem[];
    const uint32_t sb = smem_u32(smem);
    const int tid = threadIdx.x;
    const int wid = tid >> 5, lane = tid & 31;
    const int wm = wid & 3, wn = wid >> 2;
    const int m0 = blockIdx.y * 128, n0 = blockIdx.x * 128;

    float acc[2][8][4];
#pragma unroll
    for (int i = 0; i < 2; ++i)
#pragma unroll
        for (int j = 0; j < 8; ++j)
#pragma unroll
            for (int t = 0; t < 4; ++t) acc[i][j][t] = 0.0f;

    const int NC = K >> 5;

#define LOAD_CHUNK(cidx, buf)                                                  \
    do {                                                                       \
        const int k0_ = (cidx) << 5;                                           \
        const uint32_t sdst0 = sb + (buf) * BUF_SZ;                            \
        _Pragma("unroll")                                                      \
        for (int it = 0; it < 8; ++it) {                                       \
            const int comp = it >> 1;                                          \
            const int local = tid + ((it & 1) << 8);                           \
            const int r = local >> 2, ccol = local & 3;                        \
            const __nv_bfloat16* gs = (comp == 0) ? Ahi : (comp == 1) ? Alo    \
                                    : (comp == 2) ? Bhi : Blo;                 \
            const int row = ((comp < 2) ? m0 : n0) + r;                        \
            const __nv_bfloat16* gp = gs + (size_t)row * K + k0_ + ccol * 8;   \
            CP_ASYNC16(sdst0 + comp * COMP_SZ + r * ROWB + ccol * 16, gp);     \
        }                                                                      \
        CP_COMMIT();                                                           \
    } while (0)

    LOAD_CHUNK(0, 0);

    for (int c = 0; c < NC; ++c) {
        const int buf = c & 1;
        if (c + 1 < NC) { LOAD_CHUNK(c + 1, buf ^ 1); CP_WAIT1(); }
        else            { CP_WAIT0(); }
        __syncthreads();

        const uint32_t sbuf = sb + buf * BUF_SZ;
#pragma unroll
        for (int ks = 0; ks < 2; ++ks) {
            uint32_t ah[2][4], al[2][4], bf[8][2];
#pragma unroll
            for (int mi = 0; mi < 2; ++mi) {
                const uint32_t ad = (wm * 32 + mi * 16 + (lane & 15)) * ROWB
                                  + ks * 32 + ((lane >> 4) << 4);
                LDSM_X4(ah[mi][0], ah[mi][1], ah[mi][2], ah[mi][3], sbuf + ad);
                LDSM_X4(al[mi][0], al[mi][1], al[mi][2], al[mi][3],
                        sbuf + COMP_SZ + ad);
            }
#pragma unroll
            for (int p = 0; p < 4; ++p) {
                const uint32_t bd = (wn * 64 + p * 16 + ((lane >> 4) << 3) + (lane & 7)) * ROWB
                                  + ks * 32 + (((lane >> 3) & 1) << 4);
                LDSM_X4(bf[2 * p][0], bf[2 * p][1], bf[2 * p + 1][0], bf[2 * p + 1][1],
                        sbuf + 2 * COMP_SZ + bd);
            }
            // pass 1: Ahi * Bhi
#pragma unroll
            for (int mi = 0; mi < 2; ++mi)
#pragma unroll
                for (int ni = 0; ni < 8; ++ni)
                    MMA_BF16(acc[mi][ni][0], acc[mi][ni][1],
                             acc[mi][ni][2], acc[mi][ni][3],
                             ah[mi][0], ah[mi][1], ah[mi][2], ah[mi][3],
                             bf[ni][0], bf[ni][1]);
            // pass 2: Alo * Bhi
#pragma unroll
            for (int mi = 0; mi < 2; ++mi)
#pragma unroll
                for (int ni = 0; ni < 8; ++ni)
                    MMA_BF16(acc[mi][ni][0], acc[mi][ni][1],
                             acc[mi][ni][2], acc[mi][ni][3],
                             al[mi][0], al[mi][1], al[mi][2], al[mi][3],
                             bf[ni][0], bf[ni][1]);
            // reload B regs with Blo
#pragma unroll
            for (int p = 0; p < 4; ++p) {
                const uint32_t bd = (wn * 64 + p * 16 + ((lane >> 4) << 3) + (lane & 7)) * ROWB
                                  + ks * 32 + (((lane >> 3) & 1) << 4);
                LDSM_X4(bf[2 * p][0], bf[2 * p][1], bf[2 * p + 1][0], bf[2 * p + 1][1],
                        sbuf + 3 * COMP_SZ + bd);
            }
            // pass 3: Ahi * Blo
#pragma unroll
            for (int mi = 0; mi < 2; ++mi)
#pragma unroll
                for (int ni = 0; ni < 8; ++ni)
                    MMA_BF16(acc[mi][ni][0], acc[mi][ni][1],
                             acc[mi][ni][2], acc[mi][ni][3],
                             ah[mi][0], ah[mi][1], ah[mi][2], ah[mi][3],
                             bf[ni][0], bf[ni][1]);
        }
        __syncthreads();
    }

    const int tr = lane >> 2, tc = (lane & 3) << 1;
#pragma unroll
    for (int mi = 0; mi < 2; ++mi) {
        int mA = m0 + wm * 32 + mi * 16 + tr;
#pragma unroll
        for (int ni = 0; ni < 8; ++ni) {
            int n = n0 + wn * 64 + ni * 8 + tc;
            float b0 = __ldg(bias + n), b1 = __ldg(bias + n + 1);
            float v00 = acc[mi][ni][0] + b0, v01 = acc[mi][ni][1] + b1;
            float v10 = acc[mi][ni][2] + b0, v11 = acc[mi][ni][3] + b1;
            if (split_out) {
                split_store2(Chi, Clo, (size_t)mA * N + n, v00, v01);
                split_store2(Chi, Clo, (size_t)(mA + 8) * N + n, v10, v11);
            } else {
                *(float2*)(Cf + (size_t)mA * N + n) = make_float2(v00, v01);
                *(float2*)(Cf + (size_t)(mA + 8) * N + n) = make_float2(v10, v11);
            }
        }
    }
}

// ---------------- tensor-core flash attention (causal) ----------------------
// Q fragments hoisted into registers across the whole KV loop.
#define FROW 144
#define Q_SZ   (128 * FROW)
#define KV_SZ  (64 * FROW)
#define KVBUF  (4 * KV_SZ)
#define FLASH_SMEM (2 * Q_SZ + 2 * KVBUF)  // 110592

__global__ __launch_bounds__(256) void flash_attn_mma_kernel()
{
    extern __shared__ char smem[];
    const uint32_t sb = smem_u32(smem);
    const uint32_t Qhi_b = sb, Qlo_b = sb + Q_SZ;
    const uint32_t KV0 = sb + 2 * Q_SZ;

    const int tid = threadIdx.x;
    const int wid = tid >> 5, lane = tid & 31;
    const int qt = blockIdx.x, h = blockIdx.y, b = blockIdx.z;
    const int q0 = qt * 128;
    const int NT = 2 * qt + 2;

    const __nv_bfloat16* qkvhi = g_qkvhi;
    const __nv_bfloat16* qkvlo = g_qkvlo;

    {
#pragma unroll
        for (int it = 0; it < 8; ++it) {
            int gid = tid + (it << 8);
            int comp = gid >> 10;
            int rem = gid & 1023;
            int r = rem >> 3, ch = rem & 7;
            const __nv_bfloat16* src = (comp ? qkvlo : qkvhi)
                + (size_t)(b * Tt + q0 + r) * TC3 + h * DH + ch * 8;
            CP_ASYNC16((comp ? Qlo_b : Qhi_b) + r * FROW + ch * 16, src);
        }
    }
#define LOAD_KV(jt_, buf_)                                                     \
    do {                                                                       \
        const int k0_ = (jt_) * 64;                                            \
        const uint32_t base_ = KV0 + (buf_) * KVBUF;                           \
        _Pragma("unroll")                                                      \
        for (int it = 0; it < 8; ++it) {                                       \
            int gid = tid + (it << 8);                                         \
            int comp = gid >> 9;       /* 0:Khi 1:Klo 2:Vhi 3:Vlo */           \
            int rem = gid & 511;                                               \
            int r = rem >> 3, ch = rem & 7;                                    \
            int colb = ((comp < 2) ? Cc : 2 * Cc) + h * DH + ch * 8;           \
            const __nv_bfloat16* src = ((comp & 1) ? qkvlo : qkvhi)            \
                + (size_t)(b * Tt + k0_ + r) * TC3 + colb;                     \
            CP_ASYNC16(base_ + comp * KV_SZ + r * FROW + ch * 16, src);        \
        }                                                                      \
    } while (0)

    LOAD_KV(0, 0);
    CP_COMMIT();

    float o[8][4];
#pragma unroll
    for (int n = 0; n < 8; ++n)
#pragma unroll
        for (int t = 0; t < 4; ++t) o[n][t] = 0.0f;
    float m1 = -1e30f, m2 = -1e30f, l1 = 0.0f, l2 = 0.0f;

    const int row1 = q0 + wid * 16 + (lane >> 2);
    const int row2 = row1 + 8;
    const float scale = 0.125f;

    uint32_t qh[4][4], ql[4][4];  // hoisted Q fragments (kk major)

    for (int jt = 0; jt < NT; ++jt) {
        if (jt + 1 < NT) { LOAD_KV(jt + 1, (jt + 1) & 1); CP_COMMIT(); CP_WAIT1(); }
        else             { CP_WAIT0(); }
        __syncthreads();

        if (jt == 0) {
#pragma unroll
            for (int kk = 0; kk < 4; ++kk) {
                const uint32_t a_off = (wid * 16 + (lane & 15)) * FROW
                                     + kk * 32 + ((lane >> 4) << 4);
                LDSM_X4(qh[kk][0], qh[kk][1], qh[kk][2], qh[kk][3], Qhi_b + a_off);
                LDSM_X4(ql[kk][0], ql[kk][1], ql[kk][2], ql[kk][3], Qlo_b + a_off);
            }
        }

        const uint32_t kb_hi = KV0 + (jt & 1) * KVBUF;
        const uint32_t kb_lo = kb_hi + KV_SZ;
        const uint32_t vb_hi = kb_hi + 2 * KV_SZ;
        const uint32_t vb_lo = kb_hi + 3 * KV_SZ;
        const int k0 = jt * 64;

        // ---- S = Q@K^T, 3-pass hi/lo ----
        float s[8][4];
#pragma unroll
        for (int n = 0; n < 8; ++n)
#pragma unroll
            for (int t = 0; t < 4; ++t) s[n][t] = 0.0f;

#pragma unroll
        for (int kk = 0; kk < 4; ++kk) {
            uint32_t bh[8][2], bl[8][2];
#pragma unroll
            for (int p = 0; p < 4; ++p) {
                const uint32_t b_off = (p * 16 + ((lane >> 4) << 3) + (lane & 7)) * FROW
                                     + kk * 32 + (((lane >> 3) & 1) << 4);
                LDSM_X4(bh[2 * p][0], bh[2 * p][1], bh[2 * p + 1][0], bh[2 * p + 1][1],
                        kb_hi + b_off);
                LDSM_X4(bl[2 * p][0], bl[2 * p][1], bl[2 * p + 1][0], bl[2 * p + 1][1],
                        kb_lo + b_off);
            }
#pragma unroll
            for (int n = 0; n < 8; ++n) {
                MMA_BF16(s[n][0], s[n][1], s[n][2], s[n][3],
                         qh[kk][0], qh[kk][1], qh[kk][2], qh[kk][3], bh[n][0], bh[n][1]);
                MMA_BF16(s[n][0], s[n][1], s[n][2], s[n][3],
                         ql[kk][0], ql[kk][1], ql[kk][2], ql[kk][3], bh[n][0], bh[n][1]);
                MMA_BF16(s[n][0], s[n][1], s[n][2], s[n][3],
                         qh[kk][0], qh[kk][1], qh[kk][2], qh[kk][3], bl[n][0], bl[n][1]);
            }
        }

        // ---- scale + causal mask ----
        const int cb = k0 + ((lane & 3) << 1);
#pragma unroll
        for (int n = 0; n < 8; ++n) {
            int c0 = cb + n * 8, c1 = c0 + 1;
            s[n][0] = (c0 > row1) ? -1e30f : s[n][0] * scale;
            s[n][1] = (c1 > row1) ? -1e30f : s[n][1] * scale;
            s[n][2] = (c0 > row2) ? -1e30f : s[n][2] * scale;
            s[n][3] = (c1 > row2) ? -1e30f : s[n][3] * scale;
        }

        // ---- online softmax (quad reductions) ----
        float mx1 = -1e30f, mx2 = -1e30f;
#pragma unroll
        for (int n = 0; n < 8; ++n) {
            mx1 = fmaxf(mx1, fmaxf(s[n][0], s[n][1]));
            mx2 = fmaxf(mx2, fmaxf(s[n][2], s[n][3]));
        }
        mx1 = fmaxf(mx1, __shfl_xor_sync(0xffffffffu, mx1, 1));
        mx1 = fmaxf(mx1, __shfl_xor_sync(0xffffffffu, mx1, 2));
        mx2 = fmaxf(mx2, __shfl_xor_sync(0xffffffffu, mx2, 1));
        mx2 = fmaxf(mx2, __shfl_xor_sync(0xffffffffu, mx2, 2));
        float mn1 = fmaxf(m1, mx1), mn2 = fmaxf(m2, mx2);
        float rs1 = 0.0f, rs2 = 0.0f;
#pragma unroll
        for (int n = 0; n < 8; ++n) {
            s[n][0] = __expf(s[n][0] - mn1);
            s[n][1] = __expf(s[n][1] - mn1);
            s[n][2] = __expf(s[n][2] - mn2);
            s[n][3] = __expf(s[n][3] - mn2);
            rs1 += s[n][0] + s[n][1];
            rs2 += s[n][2] + s[n][3];
        }
        rs1 += __shfl_xor_sync(0xffffffffu, rs1, 1);
        rs1 += __shfl_xor_sync(0xffffffffu, rs1, 2);
        rs2 += __shfl_xor_sync(0xffffffffu, rs2, 1);
        rs2 += __shfl_xor_sync(0xffffffffu, rs2, 2);
        float al1 = __expf(m1 - mn1), al2 = __expf(m2 - mn2);
        l1 = l1 * al1 + rs1; m1 = mn1;
        l2 = l2 * al2 + rs2; m2 = mn2;
#pragma unroll
        for (int n = 0; n < 8; ++n) {
            o[n][0] *= al1; o[n][1] *= al1;
            o[n][2] *= al2; o[n][3] *= al2;
        }

        // ---- P -> bf16 hi/lo A-fragments (register-only repack) ----
        uint32_t phi[4][4], plo[4][4];
#pragma unroll
        for (int kk = 0; kk < 4; ++kk) {
            float p00 = s[2 * kk][0],     p01 = s[2 * kk][1];
            float p10 = s[2 * kk][2],     p11 = s[2 * kk][3];
            float p20 = s[2 * kk + 1][0], p21 = s[2 * kk + 1][1];
            float p30 = s[2 * kk + 1][2], p31 = s[2 * kk + 1][3];
            phi[kk][0] = pack_bf16(p00, p01);
            phi[kk][1] = pack_bf16(p10, p11);
            phi[kk][2] = pack_bf16(p20, p21);
            phi[kk][3] = pack_bf16(p30, p31);
            __nv_bfloat162* hp;
            hp = (__nv_bfloat162*)&phi[kk][0];
            plo[kk][0] = pack_bf16(p00 - __bfloat162float(hp->x), p01 - __bfloat162float(hp->y));
            hp = (__nv_bfloat162*)&phi[kk][1];
            plo[kk][1] = pack_bf16(p10 - __bfloat162float(hp->x), p11 - __bfloat162float(hp->y));
            hp = (__nv_bfloat162*)&phi[kk][2];
            plo[kk][2] = pack_bf16(p20 - __bfloat162float(hp->x), p21 - __bfloat162float(hp->y));
            hp = (__nv_bfloat162*)&phi[kk][3];
            plo[kk][3] = pack_bf16(p30 - __bfloat162float(hp->x), p31 - __bfloat162float(hp->y));
        }

        // ---- O += P@V, 3-pass (PhiVhi, PloVhi, PhiVlo) ----
#pragma unroll
        for (int kk = 0; kk < 4; ++kk) {
            uint32_t bv[8][2];
#pragma unroll
            for (int p = 0; p < 4; ++p) {
                const uint32_t v_off = (kk * 16 + (lane & 15)) * FROW
                                     + p * 32 + ((lane >> 4) << 4);
                LDSM_X4_T(bv[2 * p][0], bv[2 * p][1], bv[2 * p + 1][0], bv[2 * p + 1][1],
                          vb_hi + v_off);
            }
#pragma unroll
            for (int n = 0; n < 8; ++n) {
                MMA_BF16(o[n][0], o[n][1], o[n][2], o[n][3],
                         phi[kk][0], phi[kk][1], phi[kk][2], phi[kk][3],
                         bv[n][0], bv[n][1]);
                MMA_BF16(o[n][0], o[n][1], o[n][2], o[n][3],
                         plo[kk][0], plo[kk][1], plo[kk][2], plo[kk][3],
                         bv[n][0], bv[n][1]);
            }
#pragma unroll
            for (int p = 0; p < 4; ++p) {
                const uint32_t v_off = (kk * 16 + (lane & 15)) * FROW
                                     + p * 32 + ((lane >> 4) << 4);
                LDSM_X4_T(bv[2 * p][0], bv[2 * p][1], bv[2 * p + 1][0], bv[2 * p + 1][1],
                          vb_lo + v_off);
            }
#pragma unroll
            for (int n = 0; n < 8; ++n)
                MMA_BF16(o[n][0], o[n][1], o[n][2], o[n][3],
                         phi[kk][0], phi[kk][1], phi[kk][2], phi[kk][3],
                         bv[n][0], bv[n][1]);
        }
        __syncthreads();
    }

    // ---- normalize + write hi/lo attention output ----
    const float inv1 = 1.0f / l1, inv2 = 1.0f / l2;
    const size_t r1off = (size_t)(b * Tt + row1) * Cc + h * DH + ((lane & 3) << 1);
    const size_t r2off = (size_t)(b * Tt + row2) * Cc + h * DH + ((lane & 3) << 1);
#pragma unroll
    for (int n = 0; n < 8; ++n) {
        split_store2(g_aohi, g_aolo, r1off + n * 8, o[n][0] * inv1, o[n][1] * inv1);
        split_store2(g_aohi, g_aolo, r2off + n * 8, o[n][2] * inv2, o[n][3] * inv2);
    }
}

// ---------------------------------------------------------------------------
extern "C" void kernel_launch(void* const* d_in, const int* in_sizes, int n_in,
                              void* d_out, int out_size)
{
    const float* x     = (const float*)d_in[0];
    const float* w_qkv = (const float*)d_in[1];
    const float* b_qkv = (const float*)d_in[2];
    const float* w_out = (const float*)d_in[3];
    const float* b_out = (const float*)d_in[4];
    float* out = (float*)d_out;

    void *qkvhi_p, *qkvlo_p, *xhi_p, *xlo_p, *aohi_p, *aolo_p;
    void *wqh_p, *wql_p, *woh_p, *wol_p;
    cudaGetSymbolAddress(&qkvhi_p, g_qkvhi);
    cudaGetSymbolAddress(&qkvlo_p, g_qkvlo);
    cudaGetSymbolAddress(&xhi_p, g_xhi);
    cudaGetSymbolAddress(&xlo_p, g_xlo);
    cudaGetSymbolAddress(&aohi_p, g_aohi);
    cudaGetSymbolAddress(&aolo_p, g_aolo);
    cudaGetSymbolAddress(&wqh_p, g_wqkvT_hi);
    cudaGetSymbolAddress(&wql_p, g_wqkvT_lo);
    cudaGetSymbolAddress(&woh_p, g_woutT_hi);
    cudaGetSymbolAddress(&wol_p, g_woutT_lo);

    const size_t n4x = (size_t)MTOT * Cc / 4;

    split_kernel<<<(unsigned)((n4x + 255) / 256), 256>>>(
        x, (__nv_bfloat16*)xhi_p, (__nv_bfloat16*)xlo_p, n4x);
    transpose_split_kernel<<<dim3(TC3 / 32, Cc / 32), 256>>>(
        w_qkv, (__nv_bfloat16*)wqh_p, (__nv_bfloat16*)wql_p, Cc, TC3);
    transpose_split_kernel<<<dim3(Cc / 32, Cc / 32), 256>>>(
        w_out, (__nv_bfloat16*)woh_p, (__nv_bfloat16*)wol_p, Cc, Cc);

    cudaFuncSetAttribute(gemm_mma_kernel,
                         cudaFuncAttributeMaxDynamicSharedMemorySize, GEMM_SMEM);
    gemm_mma_kernel<<<dim3(TC3 / 128, MTOT / 128), 256, GEMM_SMEM>>>(
        (const __nv_bfloat16*)xhi_p, (const __nv_bfloat16*)xlo_p,
        (const __nv_bfloat16*)wqh_p, (const __nv_bfloat16*)wql_p,
        b_qkv, nullptr,
        (__nv_bfloat16*)qkvhi_p, (__nv_bfloat16*)qkvlo_p,
        MTOT, TC3, Cc, 1);

    cudaFuncSetAttribute(flash_attn_mma_kernel,
                         cudaFuncAttributeMaxDynamicSharedMemorySize, FLASH_SMEM);
    flash_attn_mma_kernel<<<dim3(Tt / 128, Hh, Bb), 256, FLASH_SMEM>>>();

    gemm_mma_kernel<<<dim3(Cc / 128, MTOT / 128), 256, GEMM_SMEM>>>(
        (const __nv_bfloat16*)aohi_p, (const __nv_bfloat16*)aolo_p,
        (const __nv_bfloat16*)woh_p, (const __nv_bfloat16*)wol_p,
        b_out, out, nullptr, nullptr, MTOT, Cc, Cc, 0);
}

// round 17
// speedup vs baseline: 2.6308x; 1.0842x over previous
#include <cuda_runtime.h>
#include <cuda_bf16.h>
#include <cstdint>

#define Bb 4
#define Tt 2048
#define Cc 1024
#define Hh 16
#define DH 64
#define TC3 (3*Cc)
#define MTOT (Bb*Tt)   // 8192

// ---------------- scratch (__device__ globals; no allocation allowed) -------
__device__ __nv_bfloat16 g_qkvhi[(size_t)MTOT * TC3];
__device__ __nv_bfloat16 g_qkvlo[(size_t)MTOT * TC3];
__device__ __nv_bfloat16 g_xhi [(size_t)MTOT * Cc];
__device__ __nv_bfloat16 g_xlo [(size_t)MTOT * Cc];
__device__ __nv_bfloat16 g_aohi[(size_t)MTOT * Cc];
__device__ __nv_bfloat16 g_aolo[(size_t)MTOT * Cc];
__device__ __nv_bfloat16 g_wqkvT_hi[(size_t)TC3 * Cc];
__device__ __nv_bfloat16 g_wqkvT_lo[(size_t)TC3 * Cc];
__device__ __nv_bfloat16 g_woutT_hi[(size_t)Cc * Cc];
__device__ __nv_bfloat16 g_woutT_lo[(size_t)Cc * Cc];

// ---------------- helpers ----------------------------------------------------
__device__ __forceinline__ uint32_t smem_u32(const void* p) {
    uint32_t a;
    asm("{ .reg .u64 t; cvta.to.shared.u64 t, %1; cvt.u32.u64 %0, t; }" : "=r"(a) : "l"(p));
    return a;
}
#define CP_ASYNC16(dst, src) \
    asm volatile("cp.async.cg.shared.global [%0], [%1], 16;" :: "r"(dst), "l"(src))

#define MBAR_INIT(mb, cnt) \
    asm volatile("mbarrier.init.shared.b64 [%0], %1;" :: "r"((uint32_t)(mb)), "r"((uint32_t)(cnt)) : "memory")
#define MBAR_ARRIVE(mb) \
    asm volatile("mbarrier.arrive.shared.b64 _, [%0];" :: "r"((uint32_t)(mb)) : "memory")
#define CP_ASYNC_MBAR_ARRIVE(mb) \
    asm volatile("cp.async.mbarrier.arrive.noinc.shared.b64 [%0];" :: "r"((uint32_t)(mb)) : "memory")
#define MBAR_WAIT(mb, par) do {                                                   \
    uint32_t _mb = (uint32_t)(mb), _pr = (uint32_t)(par), _done;                  \
    asm volatile("{ .reg .pred p; mbarrier.try_wait.parity.acquire.cta.shared::cta.b64 p, [%1], %2; selp.b32 %0,1,0,p; }" \
                 : "=r"(_done) : "r"(_mb), "r"(_pr) : "memory");                  \
    if (!_done) {                                                                 \
        asm volatile("{ .reg .pred P1; WL_%=: mbarrier.try_wait.parity.acquire.cta.shared::cta.b64 P1, [%0], %1, 0x989680; @P1 bra.uni WD_%=; bra.uni WL_%=; WD_%=: }" \
                     :: "r"(_mb), "r"(_pr) : "memory");                           \
    }                                                                             \
} while (0)

#define LDSM_X4(r0, r1, r2, r3, a) \
    asm volatile("ldmatrix.sync.aligned.m8n8.x4.shared.b16 {%0,%1,%2,%3}, [%4];" \
                 : "=r"(r0), "=r"(r1), "=r"(r2), "=r"(r3) : "r"(a))
#define LDSM_X4_T(r0, r1, r2, r3, a) \
    asm volatile("ldmatrix.sync.aligned.m8n8.x4.trans.shared.b16 {%0,%1,%2,%3}, [%4];" \
                 : "=r"(r0), "=r"(r1), "=r"(r2), "=r"(r3) : "r"(a))

#define MMA_BF16(c0, c1, c2, c3, a0, a1, a2, a3, b0, b1) \
    asm volatile("mma.sync.aligned.m16n8k16.row.col.f32.bf16.bf16.f32 " \
                 "{%0,%1,%2,%3}, {%4,%5,%6,%7}, {%8,%9}, {%0,%1,%2,%3};" \
                 : "+f"(c0), "+f"(c1), "+f"(c2), "+f"(c3) \
                 : "r"(a0), "r"(a1), "r"(a2), "r"(a3), "r"(b0), "r"(b1))

__device__ __forceinline__ uint32_t pack_bf16(float x, float y) {
    __nv_bfloat162 t = __floats2bfloat162_rn(x, y);
    return *reinterpret_cast<uint32_t*>(&t);
}
__device__ __forceinline__ void split_store2(__nv_bfloat16* Hi, __nv_bfloat16* Lo,
                                             size_t off, float a, float b) {
    __nv_bfloat16 h0 = __float2bfloat16(a);
    __nv_bfloat16 h1 = __float2bfloat16(b);
    float r0 = a - __bfloat162float(h0);
    float r1 = b - __bfloat162float(h1);
    ushort2 hh = make_ushort2(__bfloat16_as_ushort(h0), __bfloat16_as_ushort(h1));
    ushort2 ll = make_ushort2(__bfloat16_as_ushort(__float2bfloat16(r0)),
                              __bfloat16_as_ushort(__float2bfloat16(r1)));
    *(ushort2*)(Hi + off) = hh;
    *(ushort2*)(Lo + off) = ll;
}

// ---------------- pre-pass: fp32 -> bf16 hi/lo split ------------------------
__global__ void split_kernel(const float* __restrict__ in,
                             __nv_bfloat16* __restrict__ hi,
                             __nv_bfloat16* __restrict__ lo, size_t n4)
{
    size_t i = (size_t)blockIdx.x * blockDim.x + threadIdx.x;
    if (i >= n4) return;
    float4 v = ((const float4*)in)[i];
    ushort4 h, l;
    __nv_bfloat16 t;
    t = __float2bfloat16(v.x); h.x = __bfloat16_as_ushort(t);
    l.x = __bfloat16_as_ushort(__float2bfloat16(v.x - __bfloat162float(t)));
    t = __float2bfloat16(v.y); h.y = __bfloat16_as_ushort(t);
    l.y = __bfloat16_as_ushort(__float2bfloat16(v.y - __bfloat162float(t)));
    t = __float2bfloat16(v.z); h.z = __bfloat16_as_ushort(t);
    l.z = __bfloat16_as_ushort(__float2bfloat16(v.z - __bfloat162float(t)));
    t = __float2bfloat16(v.w); h.w = __bfloat16_as_ushort(t);
    l.w = __bfloat16_as_ushort(__float2bfloat16(v.w - __bfloat162float(t)));
    ((ushort4*)hi)[i] = h;
    ((ushort4*)lo)[i] = l;
}

// W[K,N] fp32 -> WT[N,K] bf16 hi/lo
__global__ __launch_bounds__(256) void transpose_split_kernel(
    const float* __restrict__ W, __nv_bfloat16* __restrict__ Thi,
    __nv_bfloat16* __restrict__ Tlo, int K, int N)
{
    __shared__ float tile[32][33];
    int n0 = blockIdx.x * 32, k0 = blockIdx.y * 32;
    int tx = threadIdx.x & 31, ty = threadIdx.x >> 5;
#pragma unroll
    for (int i = 0; i < 4; ++i)
        tile[ty + 8 * i][tx] = W[(size_t)(k0 + ty + 8 * i) * N + n0 + tx];
    __syncthreads();
#pragma unroll
    for (int i = 0; i < 4; ++i) {
        float v = tile[tx][ty + 8 * i];
        __nv_bfloat16 h = __float2bfloat16(v);
        __nv_bfloat16 l = __float2bfloat16(v - __bfloat162float(h));
        size_t o = (size_t)(n0 + ty + 8 * i) * K + k0 + tx;
        Thi[o] = h; Tlo[o] = l;
    }
}

// ---------------- HMMA GEMM: C = A@B^T + bias, 3-buffer mbarrier pipeline ---
// smem: [0,1024) mbars; 3 x 40KB chunk buffers (Ahi,Alo,Bhi,Blo each 128x32).
#define ROWB 80
#define COMP_SZ (128 * ROWB)
#define BUF_SZ  (4 * COMP_SZ)          // 40960
#define GEMM_SMEM (1024 + 3 * BUF_SZ)  // 123904

__global__ __launch_bounds__(256) void gemm_mma_kernel(
    const __nv_bfloat16* __restrict__ Ahi, const __nv_bfloat16* __restrict__ Alo,
    const __nv_bfloat16* __restrict__ Bhi, const __nv_bfloat16* __restrict__ Blo,
    const float* __restrict__ bias, float* __restrict__ Cf,
    __nv_bfloat16* __restrict__ Chi, __nv_bfloat16* __restrict__ Clo,
    int M, int N, int K, int split_out)
{
    extern __shared__ char smem[];
    const uint32_t sb = smem_u32(smem);
    const uint32_t mb_full = sb;       // full[b] at sb + 8b
    const uint32_t mb_empty = sb + 24; // empty[b] at sb + 24 + 8b
    const uint32_t data0 = sb + 1024;
    const int tid = threadIdx.x;
    const int wid = tid >> 5, lane = tid & 31;
    const int wm = wid & 3, wn = wid >> 2;
    const int m0 = blockIdx.y * 128, n0 = blockIdx.x * 128;

    if (tid == 0) {
#pragma unroll
        for (int i = 0; i < 3; ++i) {
            MBAR_INIT(mb_full + 8 * i, 256);
            MBAR_INIT(mb_empty + 8 * i, 256);
        }
    }
    __syncthreads();

    float acc[2][8][4];
#pragma unroll
    for (int i = 0; i < 2; ++i)
#pragma unroll
        for (int j = 0; j < 8; ++j)
#pragma unroll
            for (int t = 0; t < 4; ++t) acc[i][j][t] = 0.0f;

    const int NC = K >> 5;   // 32

#define LOAD_CHUNK(cidx, buf)                                                  \
    do {                                                                       \
        const int k0_ = (cidx) << 5;                                           \
        const uint32_t sdst0 = data0 + (buf) * BUF_SZ;                         \
        _Pragma("unroll")                                                      \
        for (int it = 0; it < 8; ++it) {                                       \
            const int comp = it >> 1;                                          \
            const int local = tid + ((it & 1) << 8);                           \
            const int r = local >> 2, ccol = local & 3;                        \
            const __nv_bfloat16* gs = (comp == 0) ? Ahi : (comp == 1) ? Alo    \
                                    : (comp == 2) ? Bhi : Blo;                 \
            const int row = ((comp < 2) ? m0 : n0) + r;                        \
            const __nv_bfloat16* gp = gs + (size_t)row * K + k0_ + ccol * 8;   \
            CP_ASYNC16(sdst0 + comp * COMP_SZ + r * ROWB + ccol * 16, gp);     \
        }                                                                      \
        CP_ASYNC_MBAR_ARRIVE(mb_full + 8 * (buf));                             \
    } while (0)

    // prologue: 3 chunks in flight
    LOAD_CHUNK(0, 0);
    LOAD_CHUNK(1, 1);
    LOAD_CHUNK(2, 2);

    for (int c = 0; c < NC; ++c) {
        const int b = c % 3;
        MBAR_WAIT(mb_full + 8 * b, (c / 3) & 1);

        const uint32_t sbuf = data0 + b * BUF_SZ;
#pragma unroll
        for (int ks = 0; ks < 2; ++ks) {
            uint32_t ah[2][4], al[2][4], bh[8][2], bl[8][2];
#pragma unroll
            for (int mi = 0; mi < 2; ++mi) {
                const uint32_t ad = (wm * 32 + mi * 16 + (lane & 15)) * ROWB
                                  + ks * 32 + ((lane >> 4) << 4);
                LDSM_X4(ah[mi][0], ah[mi][1], ah[mi][2], ah[mi][3], sbuf + ad);
                LDSM_X4(al[mi][0], al[mi][1], al[mi][2], al[mi][3],
                        sbuf + COMP_SZ + ad);
            }
#pragma unroll
            for (int p = 0; p < 4; ++p) {
                const uint32_t bd = (wn * 64 + p * 16 + ((lane >> 4) << 3) + (lane & 7)) * ROWB
                                  + ks * 32 + (((lane >> 3) & 1) << 4);
                LDSM_X4(bh[2 * p][0], bh[2 * p][1], bh[2 * p + 1][0], bh[2 * p + 1][1],
                        sbuf + 2 * COMP_SZ + bd);
                LDSM_X4(bl[2 * p][0], bl[2 * p][1], bl[2 * p + 1][0], bl[2 * p + 1][1],
                        sbuf + 3 * COMP_SZ + bd);
            }
#pragma unroll
            for (int mi = 0; mi < 2; ++mi)
#pragma unroll
                for (int ni = 0; ni < 8; ++ni)
                    MMA_BF16(acc[mi][ni][0], acc[mi][ni][1],
                             acc[mi][ni][2], acc[mi][ni][3],
                             ah[mi][0], ah[mi][1], ah[mi][2], ah[mi][3],
                             bh[ni][0], bh[ni][1]);
#pragma unroll
            for (int mi = 0; mi < 2; ++mi)
#pragma unroll
                for (int ni = 0; ni < 8; ++ni)
                    MMA_BF16(acc[mi][ni][0], acc[mi][ni][1],
                             acc[mi][ni][2], acc[mi][ni][3],
                             al[mi][0], al[mi][1], al[mi][2], al[mi][3],
                             bh[ni][0], bh[ni][1]);
#pragma unroll
            for (int mi = 0; mi < 2; ++mi)
#pragma unroll
                for (int ni = 0; ni < 8; ++ni)
                    MMA_BF16(acc[mi][ni][0], acc[mi][ni][1],
                             acc[mi][ni][2], acc[mi][ni][3],
                             ah[mi][0], ah[mi][1], ah[mi][2], ah[mi][3],
                             bl[ni][0], bl[ni][1]);
        }
        MBAR_ARRIVE(mb_empty + 8 * b);

        // refill buffer of chunk c-1 with chunk c+2 (1 chunk of slack)
        if (c >= 1 && c + 2 < NC) {
            const int b2 = (c + 2) % 3;   // == (c-1) % 3
            MBAR_WAIT(mb_empty + 8 * b2, ((c - 1) / 3) & 1);
            LOAD_CHUNK(c + 2, b2);
        }
    }

    const int tr = lane >> 2, tc = (lane & 3) << 1;
#pragma unroll
    for (int mi = 0; mi < 2; ++mi) {
        int mA = m0 + wm * 32 + mi * 16 + tr;
#pragma unroll
        for (int ni = 0; ni < 8; ++ni) {
            int n = n0 + wn * 64 + ni * 8 + tc;
            float b0 = __ldg(bias + n), b1 = __ldg(bias + n + 1);
            float v00 = acc[mi][ni][0] + b0, v01 = acc[mi][ni][1] + b1;
            float v10 = acc[mi][ni][2] + b0, v11 = acc[mi][ni][3] + b1;
            if (split_out) {
                split_store2(Chi, Clo, (size_t)mA * N + n, v00, v01);
                split_store2(Chi, Clo, (size_t)(mA + 8) * N + n, v10, v11);
            } else {
                *(float2*)(Cf + (size_t)mA * N + n) = make_float2(v00, v01);
                *(float2*)(Cf + (size_t)(mA + 8) * N + n) = make_float2(v10, v11);
            }
        }
    }
}

// ---------------- tensor-core flash attention (causal), mbar pipeline -------
#define FROW 144
#define Q_SZ   (128 * FROW)              // 18432
#define KV_SZ  (64 * FROW)               // 9216
#define KVBUF  (4 * KV_SZ)               // 36864
#define FLASH_SMEM (1024 + 2 * Q_SZ + 3 * KVBUF)  // 148480

__global__ __launch_bounds__(256) void flash_attn_mma_kernel()
{
    extern __shared__ char smem[];
    const uint32_t sb = smem_u32(smem);
    const uint32_t mb_full = sb;
    const uint32_t mb_empty = sb + 24;
    const uint32_t Qhi_b = sb + 1024, Qlo_b = Qhi_b + Q_SZ;
    const uint32_t KV0 = Qhi_b + 2 * Q_SZ;

    const int tid = threadIdx.x;
    const int wid = tid >> 5, lane = tid & 31;
    const int qt = blockIdx.x, h = blockIdx.y, b = blockIdx.z;
    const int q0 = qt * 128;
    const int NT = 2 * qt + 2;

    const __nv_bfloat16* qkvhi = g_qkvhi;
    const __nv_bfloat16* qkvlo = g_qkvlo;

    if (tid == 0) {
#pragma unroll
        for (int i = 0; i < 3; ++i) {
            MBAR_INIT(mb_full + 8 * i, 256);
            MBAR_INIT(mb_empty + 8 * i, 256);
        }
    }
    __syncthreads();

    // Q loads first (ride along with KV0's full-barrier arrival)
#pragma unroll
    for (int it = 0; it < 8; ++it) {
        int gid = tid + (it << 8);
        int comp = gid >> 10;
        int rem = gid & 1023;
        int r = rem >> 3, ch = rem & 7;
        const __nv_bfloat16* src = (comp ? qkvlo : qkvhi)
            + (size_t)(b * Tt + q0 + r) * TC3 + h * DH + ch * 8;
        CP_ASYNC16((comp ? Qlo_b : Qhi_b) + r * FROW + ch * 16, src);
    }
#define LOAD_KV(jt_, buf_)                                                     \
    do {                                                                       \
        const int k0_ = (jt_) * 64;                                            \
        const uint32_t base_ = KV0 + (buf_) * KVBUF;                           \
        _Pragma("unroll")                                                      \
        for (int it = 0; it < 8; ++it) {                                       \
            int gid = tid + (it << 8);                                         \
            int comp = gid >> 9;       /* 0:Khi 1:Klo 2:Vhi 3:Vlo */           \
            int rem = gid & 511;                                               \
            int r = rem >> 3, ch = rem & 7;                                    \
            int colb = ((comp < 2) ? Cc : 2 * Cc) + h * DH + ch * 8;           \
            const __nv_bfloat16* src = ((comp & 1) ? qkvlo : qkvhi)            \
                + (size_t)(b * Tt + k0_ + r) * TC3 + colb;                     \
            CP_ASYNC16(base_ + comp * KV_SZ + r * FROW + ch * 16, src);        \
        }                                                                      \
        CP_ASYNC_MBAR_ARRIVE(mb_full + 8 * (buf_));                            \
    } while (0)

    LOAD_KV(0, 0);
    if (1 < NT) LOAD_KV(1, 1);
    if (2 < NT) LOAD_KV(2, 2);

    float o[8][4];
#pragma unroll
    for (int n = 0; n < 8; ++n)
#pragma unroll
        for (int t = 0; t < 4; ++t) o[n][t] = 0.0f;
    float m1 = -1e30f, m2 = -1e30f, l1 = 0.0f, l2 = 0.0f;

    const int row1 = q0 + wid * 16 + (lane >> 2);
    const int row2 = row1 + 8;
    const float scale = 0.125f;

    uint32_t qh[4][4], ql[4][4];

    for (int jt = 0; jt < NT; ++jt) {
        const int kb = jt % 3;
        MBAR_WAIT(mb_full + 8 * kb, (jt / 3) & 1);

        if (jt == 0) {
#pragma unroll
            for (int kk = 0; kk < 4; ++kk) {
                const uint32_t a_off = (wid * 16 + (lane & 15)) * FROW
                                     + kk * 32 + ((lane >> 4) << 4);
                LDSM_X4(qh[kk][0], qh[kk][1], qh[kk][2], qh[kk][3], Qhi_b + a_off);
                LDSM_X4(ql[kk][0], ql[kk][1], ql[kk][2], ql[kk][3], Qlo_b + a_off);
            }
        }

        const uint32_t kb_hi = KV0 + kb * KVBUF;
        const uint32_t kb_lo = kb_hi + KV_SZ;
        const uint32_t vb_hi = kb_hi + 2 * KV_SZ;
        const uint32_t vb_lo = kb_hi + 3 * KV_SZ;
        const int k0 = jt * 64;

        // ---- S = Q@K^T, 3-pass hi/lo ----
        float s[8][4];
#pragma unroll
        for (int n = 0; n < 8; ++n)
#pragma unroll
            for (int t = 0; t < 4; ++t) s[n][t] = 0.0f;

#pragma unroll
        for (int kk = 0; kk < 4; ++kk) {
            uint32_t bh[8][2], bl[8][2];
#pragma unroll
            for (int p = 0; p < 4; ++p) {
                const uint32_t b_off = (p * 16 + ((lane >> 4) << 3) + (lane & 7)) * FROW
                                     + kk * 32 + (((lane >> 3) & 1) << 4);
                LDSM_X4(bh[2 * p][0], bh[2 * p][1], bh[2 * p + 1][0], bh[2 * p + 1][1],
                        kb_hi + b_off);
                LDSM_X4(bl[2 * p][0], bl[2 * p][1], bl[2 * p + 1][0], bl[2 * p + 1][1],
                        kb_lo + b_off);
            }
#pragma unroll
            for (int n = 0; n < 8; ++n) {
                MMA_BF16(s[n][0], s[n][1], s[n][2], s[n][3],
                         qh[kk][0], qh[kk][1], qh[kk][2], qh[kk][3], bh[n][0], bh[n][1]);
                MMA_BF16(s[n][0], s[n][1], s[n][2], s[n][3],
                         ql[kk][0], ql[kk][1], ql[kk][2], ql[kk][3], bh[n][0], bh[n][1]);
                MMA_BF16(s[n][0], s[n][1], s[n][2], s[n][3],
                         qh[kk][0], qh[kk][1], qh[kk][2], qh[kk][3], bl[n][0], bl[n][1]);
            }
        }

        // ---- scale + causal mask ----
        const int cb = k0 + ((lane & 3) << 1);
#pragma unroll
        for (int n = 0; n < 8; ++n) {
            int c0 = cb + n * 8, c1 = c0 + 1;
            s[n][0] = (c0 > row1) ? -1e30f : s[n][0] * scale;
            s[n][1] = (c1 > row1) ? -1e30f : s[n][1] * scale;
            s[n][2] = (c0 > row2) ? -1e30f : s[n][2] * scale;
            s[n][3] = (c1 > row2) ? -1e30f : s[n][3] * scale;
        }

        // ---- online softmax (quad reductions) ----
        float mx1 = -1e30f, mx2 = -1e30f;
#pragma unroll
        for (int n = 0; n < 8; ++n) {
            mx1 = fmaxf(mx1, fmaxf(s[n][0], s[n][1]));
            mx2 = fmaxf(mx2, fmaxf(s[n][2], s[n][3]));
        }
        mx1 = fmaxf(mx1, __shfl_xor_sync(0xffffffffu, mx1, 1));
        mx1 = fmaxf(mx1, __shfl_xor_sync(0xffffffffu, mx1, 2));
        mx2 = fmaxf(mx2, __shfl_xor_sync(0xffffffffu, mx2, 1));
        mx2 = fmaxf(mx2, __shfl_xor_sync(0xffffffffu, mx2, 2));
        float mn1 = fmaxf(m1, mx1), mn2 = fmaxf(m2, mx2);
        float rs1 = 0.0f, rs2 = 0.0f;
#pragma unroll
        for (int n = 0; n < 8; ++n) {
            s[n][0] = __expf(s[n][0] - mn1);
            s[n][1] = __expf(s[n][1] - mn1);
            s[n][2] = __expf(s[n][2] - mn2);
            s[n][3] = __expf(s[n][3] - mn2);
            rs1 += s[n][0] + s[n][1];
            rs2 += s[n][2] + s[n][3];
        }
        rs1 += __shfl_xor_sync(0xffffffffu, rs1, 1);
        rs1 += __shfl_xor_sync(0xffffffffu, rs1, 2);
        rs2 += __shfl_xor_sync(0xffffffffu, rs2, 1);
        rs2 += __shfl_xor_sync(0xffffffffu, rs2, 2);
        float al1 = __expf(m1 - mn1), al2 = __expf(m2 - mn2);
        l1 = l1 * al1 + rs1; m1 = mn1;
        l2 = l2 * al2 + rs2; m2 = mn2;
#pragma unroll
        for (int n = 0; n < 8; ++n) {
            o[n][0] *= al1; o[n][1] *= al1;
            o[n][2] *= al2; o[n][3] *= al2;
        }

        // ---- P -> bf16 hi/lo A-fragments ----
        uint32_t phi[4][4], plo[4][4];
#pragma unroll
        for (int kk = 0; kk < 4; ++kk) {
            float p00 = s[2 * kk][0],     p01 = s[2 * kk][1];
            float p10 = s[2 * kk][2],     p11 = s[2 * kk][3];
            float p20 = s[2 * kk + 1][0], p21 = s[2 * kk + 1][1];
            float p30 = s[2 * kk + 1][2], p31 = s[2 * kk + 1][3];
            phi[kk][0] = pack_bf16(p00, p01);
            phi[kk][1] = pack_bf16(p10, p11);
            phi[kk][2] = pack_bf16(p20, p21);
            phi[kk][3] = pack_bf16(p30, p31);
            __nv_bfloat162* hp;
            hp = (__nv_bfloat162*)&phi[kk][0];
            plo[kk][0] = pack_bf16(p00 - __bfloat162float(hp->x), p01 - __bfloat162float(hp->y));
            hp = (__nv_bfloat162*)&phi[kk][1];
            plo[kk][1] = pack_bf16(p10 - __bfloat162float(hp->x), p11 - __bfloat162float(hp->y));
            hp = (__nv_bfloat162*)&phi[kk][2];
            plo[kk][2] = pack_bf16(p20 - __bfloat162float(hp->x), p21 - __bfloat162float(hp->y));
            hp = (__nv_bfloat162*)&phi[kk][3];
            plo[kk][3] = pack_bf16(p30 - __bfloat162float(hp->x), p31 - __bfloat162float(hp->y));
        }

        // ---- O += P@V, 3-pass, V hi+lo fragments preloaded ----
#pragma unroll
        for (int kk = 0; kk < 4; ++kk) {
            uint32_t bvh[8][2], bvl[8][2];
#pragma unroll
            for (int p = 0; p < 4; ++p) {
                const uint32_t v_off = (kk * 16 + (lane & 15)) * FROW
                                     + p * 32 + ((lane >> 4) << 4);
                LDSM_X4_T(bvh[2 * p][0], bvh[2 * p][1], bvh[2 * p + 1][0], bvh[2 * p + 1][1],
                          vb_hi + v_off);
                LDSM_X4_T(bvl[2 * p][0], bvl[2 * p][1], bvl[2 * p + 1][0], bvl[2 * p + 1][1],
                          vb_lo + v_off);
            }
#pragma unroll
            for (int n = 0; n < 8; ++n) {
                MMA_BF16(o[n][0], o[n][1], o[n][2], o[n][3],
                         phi[kk][0], phi[kk][1], phi[kk][2], phi[kk][3],
                         bvh[n][0], bvh[n][1]);
                MMA_BF16(o[n][0], o[n][1], o[n][2], o[n][3],
                         plo[kk][0], plo[kk][1], plo[kk][2], plo[kk][3],
                         bvh[n][0], bvh[n][1]);
                MMA_BF16(o[n][0], o[n][1], o[n][2], o[n][3],
                         phi[kk][0], phi[kk][1], phi[kk][2], phi[kk][3],
                         bvl[n][0], bvl[n][1]);
            }
        }

        MBAR_ARRIVE(mb_empty + 8 * kb);
        if (jt >= 1 && jt + 2 < NT) {
            const int b2 = (jt + 2) % 3;   // == (jt-1) % 3
            MBAR_WAIT(mb_empty + 8 * b2, ((jt - 1) / 3) & 1);
            LOAD_KV(jt + 2, b2);
        }
    }

    // ---- normalize + write hi/lo attention output ----
    const float inv1 = 1.0f / l1, inv2 = 1.0f / l2;
    const size_t r1off = (size_t)(b * Tt + row1) * Cc + h * DH + ((lane & 3) << 1);
    const size_t r2off = (size_t)(b * Tt + row2) * Cc + h * DH + ((lane & 3) << 1);
#pragma unroll
    for (int n = 0; n < 8; ++n) {
        split_store2(g_aohi, g_aolo, r1off + n * 8, o[n][0] * inv1, o[n][1] * inv1);
        split_store2(g_aohi, g_aolo, r2off + n * 8, o[n][2] * inv2, o[n][3] * inv2);
    }
}

// ---------------------------------------------------------------------------
extern "C" void kernel_launch(void* const* d_in, const int* in_sizes, int n_in,
                              void* d_out, int out_size)
{
    const float* x     = (const float*)d_in[0];
    const float* w_qkv = (const float*)d_in[1];
    const float* b_qkv = (const float*)d_in[2];
    const float* w_out = (const float*)d_in[3];
    const float* b_out = (const float*)d_in[4];
    float* out = (float*)d_out;

    void *qkvhi_p, *qkvlo_p, *xhi_p, *xlo_p, *aohi_p, *aolo_p;
    void *wqh_p, *wql_p, *woh_p, *wol_p;
    cudaGetSymbolAddress(&qkvhi_p, g_qkvhi);
    cudaGetSymbolAddress(&qkvlo_p, g_qkvlo);
    cudaGetSymbolAddress(&xhi_p, g_xhi);
    cudaGetSymbolAddress(&xlo_p, g_xlo);
    cudaGetSymbolAddress(&aohi_p, g_aohi);
    cudaGetSymbolAddress(&aolo_p, g_aolo);
    cudaGetSymbolAddress(&wqh_p, g_wqkvT_hi);
    cudaGetSymbolAddress(&wql_p, g_wqkvT_lo);
    cudaGetSymbolAddress(&woh_p, g_woutT_hi);
    cudaGetSymbolAddress(&wol_p, g_woutT_lo);

    const size_t n4x = (size_t)MTOT * Cc / 4;

    split_kernel<<<(unsigned)((n4x + 255) / 256), 256>>>(
        x, (__nv_bfloat16*)xhi_p, (__nv_bfloat16*)xlo_p, n4x);
    transpose_split_kernel<<<dim3(TC3 / 32, Cc / 32), 256>>>(
        w_qkv, (__nv_bfloat16*)wqh_p, (__nv_bfloat16*)wql_p, Cc, TC3);
    transpose_split_kernel<<<dim3(Cc / 32, Cc / 32), 256>>>(
        w_out, (__nv_bfloat16*)woh_p, (__nv_bfloat16*)wol_p, Cc, Cc);

    cudaFuncSetAttribute(gemm_mma_kernel,
                         cudaFuncAttributeMaxDynamicSharedMemorySize, GEMM_SMEM);
    gemm_mma_kernel<<<dim3(TC3 / 128, MTOT / 128), 256, GEMM_SMEM>>>(
        (const __nv_bfloat16*)xhi_p, (const __nv_bfloat16*)xlo_p,
        (const __nv_bfloat16*)wqh_p, (const __nv_bfloat16*)wql_p,
        b_qkv, nullptr,
        (__nv_bfloat16*)qkvhi_p, (__nv_bfloat16*)qkvlo_p,
        MTOT, TC3, Cc, 1);

    cudaFuncSetAttribute(flash_attn_mma_kernel,
                         cudaFuncAttributeMaxDynamicSharedMemorySize, FLASH_SMEM);
    flash_attn_mma_kernel<<<dim3(Tt / 128, Hh, Bb), 256, FLASH_SMEM>>>();

    gemm_mma_kernel<<<dim3(Cc / 128, MTOT / 128), 256, GEMM_SMEM>>>(
        (const __nv_bfloat16*)aohi_p, (const __nv_bfloat16*)aolo_p,
        (const __nv_bfloat16*)woh_p, (const __nv_bfloat16*)wol_p,
        b_out, out, nullptr, nullptr, MTOT, Cc, Cc, 0);
}